// round 13
// baseline (speedup 1.0000x reference)
#include <cuda_runtime.h>
#include <cuda_fp16.h>
#include <math.h>
#include <stdint.h>

#define NE 50000
#define NN 25000
#define NG 1024
#define HID 128
#define NTILES 391

// layers 2/3 msg smem: A [128x272B] | B buf0 | buf1 | buf2 (each 64x272B)
#define SM_B      34816
#define SM_BUF    17408
#define SMEM_BYTES 87040
// layer-1 2-tile msg smem: A0 | A1 | B buf0 | B buf1
#define SM2_A1    34816
#define SM2_B     69632
#define SM2_BUF   17408
#define SMEM2_BYTES 104448

__device__ __align__(256) unsigned char g_w2s[103 * 16384];   // fp16 w2T chunks [64x256B]
__device__ float g_fa[NN * 64];
__device__ float g_fb[NN * 64];
__device__ float g_acc[NN * 64];
__device__ float g_acc2[NN * 64];
__device__ float g_y[NN * 64];
__device__ float g_sums[NG * 64];
__device__ float g_cnt[NG];
__device__ int g_src[NE], g_dst[NE], g_batch[NN];

__device__ __forceinline__ float eluf(float v) { return v > 0.f ? v : expm1f(v); }
__device__ __forceinline__ uint32_t s2u(const void* p) {
    uint32_t a;
    asm("{ .reg .u64 t; cvta.to.shared.u64 t, %1; cvt.u32.u64 %0, t; }" : "=r"(a) : "l"(p));
    return a;
}
__device__ __forceinline__ void cp16(uint32_t s, const void* g) {
    asm volatile("cp.async.cg.shared.global [%0], [%1], 16;" :: "r"(s), "l"(g));
}
__device__ __forceinline__ void cp_commit() { asm volatile("cp.async.commit_group;" ::: "memory"); }
template<int N> __device__ __forceinline__ void cp_wait() { asm volatile("cp.async.wait_group %0;" :: "n"(N) : "memory"); }
__device__ __forceinline__ void ldsm4(uint32_t* r, uint32_t a) {
    asm volatile("ldmatrix.sync.aligned.m8n8.x4.shared.b16 {%0,%1,%2,%3}, [%4];"
                 : "=r"(r[0]), "=r"(r[1]), "=r"(r[2]), "=r"(r[3]) : "r"(a));
}
__device__ __forceinline__ void mma16816(float* d, const uint32_t* a, uint32_t b0, uint32_t b1) {
    asm volatile("mma.sync.aligned.m16n8k16.row.col.f32.f16.f16.f32 "
                 "{%0,%1,%2,%3}, {%4,%5,%6,%7}, {%8,%9}, {%0,%1,%2,%3};"
                 : "+f"(d[0]), "+f"(d[1]), "+f"(d[2]), "+f"(d[3])
                 : "r"(a[0]), "r"(a[1]), "r"(a[2]), "r"(a[3]), "r"(b0), "r"(b1));
}

// ---------------- merged prep: convert + w2prep + layer-1 rootxb2 ----------
// Independent work partitioned by block range (no intra-warp divergence).
#define PREP_B_CONV 256          // 65536 threads: convert + pool-zero
#define PREP_B_W2   3296         // 843776 threads: w2 chunk tiles
#define PREP_B_ROOT 3125         // 800000 threads: rootxb2<13,32>
__global__ void prep_kernel(const void* __restrict__ ei, const void* __restrict__ bat,
                            const float* __restrict__ w2a, const float* __restrict__ w2b,
                            const float* __restrict__ w2c,
                            const float* __restrict__ x, const float* __restrict__ root,
                            const float* __restrict__ bias, const float* __restrict__ b2,
                            float* __restrict__ acc) {
    const int b = blockIdx.x;
    if (b < PREP_B_CONV) {
        const long long* e64 = (const long long*)ei;
        int is64 = 1;
#pragma unroll
        for (int i = 0; i < 32; i++) {
            long long v = e64[i];
            if (v < 0 || v >= (long long)NN) { is64 = 0; break; }
        }
        int t = b * 256 + threadIdx.x;
        if (t < NE) {
            if (is64) { g_src[t] = (int)((const long long*)ei)[t]; g_dst[t] = (int)((const long long*)ei)[NE + t]; }
            else      { g_src[t] = ((const int*)ei)[t];            g_dst[t] = ((const int*)ei)[NE + t]; }
        }
        if (t < NN) g_batch[t] = is64 ? (int)((const long long*)bat)[t] : ((const int*)bat)[t];
        if (t < NG * 64) g_sums[t] = 0.f;
        if (t < NG) g_cnt[t] = 0.f;
    } else if (b < PREP_B_CONV + PREP_B_W2) {
        int t = (b - PREP_B_CONV) * 256 + threadIdx.x;
        if (t >= 103 * 8192) return;
        int c = t >> 13, rem = t & 8191, r = rem >> 7, k = rem & 127;
        const float* w2; int cb, sz;
        if (c < 7)       { w2 = w2a; cb = 0;  sz = 13 * 32; }
        else if (c < 39) { w2 = w2b; cb = 7;  sz = 32 * 64; }
        else             { w2 = w2c; cb = 39; sz = 64 * 64; }
        int n = (c - cb) * 64 + r;
        float v = (n < sz) ? w2[k * sz + n] : 0.f;
        *(__half*)(g_w2s + (size_t)c * 16384 + r * 256 + k * 2) = __float2half(v);
    } else {
        int t = (b - PREP_B_CONV - PREP_B_W2) * 256 + threadIdx.x;
        if (t >= NN * 32) return;
        int n = t >> 5, o = t & 31;
        const float* xr = x + n * 13;
        float s = bias[o], y = 0.f;
#pragma unroll
        for (int i = 0; i < 13; i++) {
            float xv = xr[i];
            s = fmaf(xv, root[i * 32 + o], s);
            y = fmaf(xv, b2[i * 32 + o], y);
        }
        acc[t] = s;
        g_y[t] = y;
    }
}

// -------- layer transition: f = elu(acc_in); acc_out = f@root+bias; y = f@b2
template<int MI>
__global__ void __launch_bounds__(256)
trans_kernel(const float* __restrict__ acc_in, float* __restrict__ fout,
             const float* __restrict__ root, const float* __restrict__ bias,
             const float* __restrict__ b2, float* __restrict__ acc_out) {
    __shared__ float f[4][MI];
    const int tid = threadIdx.x;
    const int n0 = blockIdx.x * 4;
    if (tid < 4 * MI) {
        int n = tid / MI, i = tid - n * MI;
        float v = eluf(acc_in[(size_t)(n0 + n) * MI + i]);
        f[n][i] = v;
        fout[(size_t)(n0 + n) * MI + i] = v;
    }
    __syncthreads();
    const int n = tid >> 6, o = tid & 63;
    float s = bias[o], y = 0.f;
#pragma unroll
    for (int i = 0; i < MI; i++) {
        float fv = f[n][i];
        s = fmaf(fv, root[i * 64 + o], s);
        y = fmaf(fv, b2[i * 64 + o], y);
    }
    acc_out[(size_t)(n0 + n) * 64 + o] = s;
    g_y[(size_t)(n0 + n) * 64 + o] = y;
}

// -------- layer-3 elu + pooling with run-length aggregation ----------------
__global__ void __launch_bounds__(256)
elu_pool_kernel(const float* __restrict__ acc) {
    const int tid = threadIdx.x;
    const int o = tid & 63;
    const int grp = tid >> 6;
    const int n0 = blockIdx.x * 32 + grp * 8;
    float s = 0.f;
    int curg = -1;
    for (int j = 0; j < 8; j++) {
        const int n = n0 + j;
        if (n >= NN) break;
        const int g = g_batch[n];
        const float v = eluf(acc[(size_t)n * 64 + o]);
        if (g != curg) {
            if (curg >= 0) atomicAdd(&g_sums[curg * 64 + o], s);
            curg = g; s = v;
        } else s += v;
    }
    if (curg >= 0) atomicAdd(&g_sums[curg * 64 + o], s);
    if (o == 0) {
        float c = 0.f; int cg = -1;
        for (int j = 0; j < 8; j++) {
            const int n = n0 + j;
            if (n >= NN) break;
            const int g = g_batch[n];
            if (g != cg) { if (cg >= 0) atomicAdd(&g_cnt[cg], c); cg = g; c = 1.f; }
            else c += 1.f;
        }
        if (cg >= 0) atomicAdd(&g_cnt[cg], c);
    }
}

__device__ __forceinline__ void copyB(int cabs, uint32_t dst, int tid) {
    const unsigned char* gb = g_w2s + (size_t)cabs * 16384;
    for (int idx = tid; idx < 1024; idx += 256) {
        int r = idx >> 4, s = idx & 15;
        cp16(dst + r * 272 + s * 16, gb + r * 256 + s * 16);
    }
}

// -------- LAYER-1 msg: 2 tiles per CTA, shared B pipeline ------------------
// Prologue (ea stage, h compute, w1 reg load) amortized over 2 tiles; grid
// 196 <= 296 slots. Per-chunk x-fold shrinks av to 16 regs/tile.
__global__ void __launch_bounds__(256, 2)
msg_mma1_kernel(const float* __restrict__ xin, float* __restrict__ acc,
                const float* __restrict__ ea,
                const float* __restrict__ w1, const float* __restrict__ b1) {
    constexpr int NC = 7;
    extern __shared__ char smem[];
    __shared__ float eas[1280];
    const uint32_t sb = s2u(smem);
    const int tid = threadIdx.x, wid = tid >> 5, lane = tid & 31;
    const int t0 = blockIdx.x * 2;
    const bool has1 = (t0 + 1 < NTILES);

    copyB(0, sb + SM2_B, tid);
    cp_commit();
    copyB(1, sb + SM2_B + SM2_BUF, tid);
    cp_commit();

    {
        const int gbase = t0 * 640;
        for (int idx = tid; idx < 1280; idx += 256)
            eas[idx] = (gbase + idx < NE * 5) ? ea[gbase + idx] : 0.f;
    }

    const int kp = tid & 63, k2 = kp * 2;
    float wv[10], bv0, bv1;
#pragma unroll
    for (int d = 0; d < 5; d++) {
        wv[2 * d]     = w1[d * HID + k2];
        wv[2 * d + 1] = w1[d * HID + k2 + 1];
    }
    bv0 = b1[k2]; bv1 = b1[k2 + 1];
    __syncthreads();

    // h for both tiles
    {
        const int rbase = tid >> 6;
#pragma unroll
        for (int tt = 0; tt < 2; tt++) {
            const int ecnt = min(128, NE - (t0 + tt) * 128);
#pragma unroll 8
            for (int j = 0; j < 32; j++) {
                const int r = rbase + 4 * j;
                uint32_t packed = 0;
                if (r < ecnt) {
                    const float* a = eas + (tt * 128 + r) * 5;
                    float s0 = bv0, s1 = bv1;
                    s0 = fmaf(a[0], wv[0], s0); s1 = fmaf(a[0], wv[1], s1);
                    s0 = fmaf(a[1], wv[2], s0); s1 = fmaf(a[1], wv[3], s1);
                    s0 = fmaf(a[2], wv[4], s0); s1 = fmaf(a[2], wv[5], s1);
                    s0 = fmaf(a[3], wv[6], s0); s1 = fmaf(a[3], wv[7], s1);
                    s0 = fmaf(a[4], wv[8], s0); s1 = fmaf(a[4], wv[9], s1);
                    s0 = fmaxf(s0, 0.f); s1 = fmaxf(s1, 0.f);
                    __half h0 = __float2half(s0), h1 = __float2half(s1);
                    packed = ((uint32_t)__half_as_ushort(h1) << 16) | __half_as_ushort(h0);
                }
                *(uint32_t*)(smem + tt * SM2_A1 + r * 272 + kp * 4) = packed;
            }
        }
    }

    const int m0 = wid * 16;
    const int r0 = lane >> 2;
    int srcA[2][2], dstA[2][2];
#pragma unroll
    for (int tt = 0; tt < 2; tt++) {
        const int e0 = (t0 + tt) * 128 + m0 + r0;
        const int e1 = e0 + 8;
        srcA[tt][0] = (e0 < NE) ? g_src[e0] : 0;
        dstA[tt][0] = (e0 < NE) ? g_dst[e0] : -1;
        srcA[tt][1] = (e1 < NE) ? g_src[e1] : 0;
        dstA[tt][1] = (e1 < NE) ? g_dst[e1] : -1;
    }

    const uint32_t lrow = (lane & 15);
    const uint32_t kh16 = (lane >> 4) * 16;

    float av[2][4][4];
#pragma unroll
    for (int tt = 0; tt < 2; tt++)
#pragma unroll
        for (int nb = 0; nb < 4; nb++)
#pragma unroll
            for (int q = 0; q < 4; q++) av[tt][nb][q] = 0.f;

    for (int c = 0; c < NC; c++) {
        if (c + 1 == NC) cp_wait<0>(); else cp_wait<1>();
        __syncthreads();
        const uint32_t Bb = sb + SM2_B + (uint32_t)(c & 1) * SM2_BUF;
        const int i0 = min(2 * c, 12), i1 = min(2 * c + 1, 12);

        const int ntt = has1 ? 2 : 1;
        for (int tt = 0; tt < ntt; tt++) {
            float d[8][4];
#pragma unroll
            for (int nb = 0; nb < 8; nb++)
#pragma unroll
                for (int q = 0; q < 4; q++) d[nb][q] = 0.f;
            const uint32_t Ab = sb + (uint32_t)tt * SM2_A1;
#pragma unroll
            for (int ks = 0; ks < 8; ks++) {
                uint32_t a[4];
                ldsm4(a, Ab + (m0 + lrow) * 272 + ks * 32 + kh16);
#pragma unroll
                for (int nb2 = 0; nb2 < 4; nb2++) {
                    uint32_t b[4];
                    ldsm4(b, Bb + (nb2 * 16 + lrow) * 272 + ks * 32 + kh16);
                    mma16816(d[2 * nb2],     a, b[0], b[2]);
                    mma16816(d[2 * nb2 + 1], a, b[1], b[3]);
                }
            }
            const float x00 = xin[(size_t)srcA[tt][0] * 13 + i0];
            const float x01 = xin[(size_t)srcA[tt][0] * 13 + i1];
            const float x10 = xin[(size_t)srcA[tt][1] * 13 + i0];
            const float x11 = xin[(size_t)srcA[tt][1] * 13 + i1];
#pragma unroll
            for (int nb = 0; nb < 4; nb++) {
                av[tt][nb][0] += x00 * d[nb][0] + x01 * d[nb + 4][0];
                av[tt][nb][1] += x00 * d[nb][1] + x01 * d[nb + 4][1];
                av[tt][nb][2] += x10 * d[nb][2] + x11 * d[nb + 4][2];
                av[tt][nb][3] += x10 * d[nb][3] + x11 * d[nb + 4][3];
            }
        }
        __syncthreads();               // readers done before refill of (c&1)
        if (c + 2 < NC) { copyB(c + 2, sb + SM2_B + (uint32_t)(c & 1) * SM2_BUF, tid); cp_commit(); }
    }

    const int oc = (lane & 3) * 2;
#pragma unroll
    for (int tt = 0; tt < 2; tt++) {
#pragma unroll
        for (int nb = 0; nb < 4; nb++) {
            const int o = nb * 8 + oc;
            const int d0 = dstA[tt][0], s0i = srcA[tt][0];
            const int d1 = dstA[tt][1], s1i = srcA[tt][1];
            if (d0 >= 0) {
                atomicAdd(acc + (size_t)d0 * 32 + o,     av[tt][nb][0] + g_y[(size_t)s0i * 32 + o]);
                atomicAdd(acc + (size_t)d0 * 32 + o + 1, av[tt][nb][1] + g_y[(size_t)s0i * 32 + o + 1]);
            }
            if (d1 >= 0) {
                atomicAdd(acc + (size_t)d1 * 32 + o,     av[tt][nb][2] + g_y[(size_t)s1i * 32 + o]);
                atomicAdd(acc + (size_t)d1 * 32 + o + 1, av[tt][nb][3] + g_y[(size_t)s1i * 32 + o + 1]);
            }
        }
    }
}

// -------- layers 2/3 msg (R12 winner: fused h prologue, 3-buffer) ----------
template<int M_IN, int NC, int CBASE>
__global__ void __launch_bounds__(256, 2)
msg_mma_kernel(const float* __restrict__ xin, float* __restrict__ acc,
               const float* __restrict__ ea,
               const float* __restrict__ w1, const float* __restrict__ b1) {
    extern __shared__ char smem[];
    __shared__ float eas[640];
    const uint32_t sb = s2u(smem);
    const int tid = threadIdx.x, wid = tid >> 5, lane = tid & 31;
    const int tile = blockIdx.x;

    copyB(CBASE, sb + SM_B, tid);
    cp_commit();
    copyB(CBASE + 1, sb + SM_B + SM_BUF, tid);
    cp_commit();

    {
        const int gbase = tile * 640;
        for (int idx = tid; idx < 640; idx += 256)
            eas[idx] = (gbase + idx < NE * 5) ? ea[gbase + idx] : 0.f;
    }

    const int kp = tid & 63, k2 = kp * 2;
    float wv[10], bv0, bv1;
#pragma unroll
    for (int d = 0; d < 5; d++) {
        wv[2 * d]     = w1[d * HID + k2];
        wv[2 * d + 1] = w1[d * HID + k2 + 1];
    }
    bv0 = b1[k2]; bv1 = b1[k2 + 1];
    __syncthreads();

    {
        const int rbase = tid >> 6;
        const int ecnt = min(128, NE - tile * 128);
#pragma unroll 8
        for (int j = 0; j < 32; j++) {
            const int r = rbase + 4 * j;
            uint32_t packed = 0;
            if (r < ecnt) {
                const float* a = eas + r * 5;
                float s0 = bv0, s1 = bv1;
                s0 = fmaf(a[0], wv[0], s0); s1 = fmaf(a[0], wv[1], s1);
                s0 = fmaf(a[1], wv[2], s0); s1 = fmaf(a[1], wv[3], s1);
                s0 = fmaf(a[2], wv[4], s0); s1 = fmaf(a[2], wv[5], s1);
                s0 = fmaf(a[3], wv[6], s0); s1 = fmaf(a[3], wv[7], s1);
                s0 = fmaf(a[4], wv[8], s0); s1 = fmaf(a[4], wv[9], s1);
                s0 = fmaxf(s0, 0.f); s1 = fmaxf(s1, 0.f);
                __half h0 = __float2half(s0), h1 = __float2half(s1);
                packed = ((uint32_t)__half_as_ushort(h1) << 16) | __half_as_ushort(h0);
            }
            *(uint32_t*)(smem + r * 272 + kp * 4) = packed;
        }
    }

    const int m0 = wid * 16;
    const int r0 = lane >> 2;
    const int e0 = tile * 128 + m0 + r0;
    const int e1 = e0 + 8;
    int src0 = 0, dst0 = -1, src1 = 0, dst1 = -1;
    if (e0 < NE) { src0 = g_src[e0]; dst0 = g_dst[e0]; }
    if (e1 < NE) { src1 = g_src[e1]; dst1 = g_dst[e1]; }

    const uint32_t lrow = (lane & 15);
    const uint32_t kh16 = (lane >> 4) * 16;

    float av[8][4];
#pragma unroll
    for (int nb = 0; nb < 8; nb++)
#pragma unroll
        for (int q = 0; q < 4; q++) av[nb][q] = 0.f;

    int bufc = 0;
    for (int c = 0; c < NC; c++) {
        if (c + 1 == NC) cp_wait<0>(); else cp_wait<1>();
        __syncthreads();

        if (c + 2 < NC) {
            int b2i = bufc + 2; if (b2i >= 3) b2i -= 3;
            copyB(CBASE + c + 2, sb + SM_B + (uint32_t)b2i * SM_BUF, tid);
            cp_commit();
        }

        const uint32_t Bb = sb + SM_B + (uint32_t)bufc * SM_BUF;
        if (++bufc == 3) bufc = 0;
        float d[8][4];
#pragma unroll
        for (int nb = 0; nb < 8; nb++)
#pragma unroll
            for (int q = 0; q < 4; q++) d[nb][q] = 0.f;

#pragma unroll
        for (int ks = 0; ks < 8; ks++) {
            uint32_t a[4];
            ldsm4(a, sb + (m0 + lrow) * 272 + ks * 32 + kh16);
#pragma unroll
            for (int nb2 = 0; nb2 < 4; nb2++) {
                uint32_t b[4];
                ldsm4(b, Bb + (nb2 * 16 + lrow) * 272 + ks * 32 + kh16);
                mma16816(d[2 * nb2],     a, b[0], b[2]);
                mma16816(d[2 * nb2 + 1], a, b[1], b[3]);
            }
        }

        const float xs0 = xin[(size_t)src0 * M_IN + c];
        const float xs1 = xin[(size_t)src1 * M_IN + c];
#pragma unroll
        for (int nb = 0; nb < 8; nb++) {
            av[nb][0] = fmaf(xs0, d[nb][0], av[nb][0]);
            av[nb][1] = fmaf(xs0, d[nb][1], av[nb][1]);
            av[nb][2] = fmaf(xs1, d[nb][2], av[nb][2]);
            av[nb][3] = fmaf(xs1, d[nb][3], av[nb][3]);
        }
    }

    const int oc = (lane & 3) * 2;
#pragma unroll
    for (int nb = 0; nb < 8; nb++) {
        const int o = nb * 8 + oc;
        if (dst0 >= 0) {
            atomicAdd(acc + (size_t)dst0 * 64 + o,     av[nb][0] + g_y[(size_t)src0 * 64 + o]);
            atomicAdd(acc + (size_t)dst0 * 64 + o + 1, av[nb][1] + g_y[(size_t)src0 * 64 + o + 1]);
        }
        if (dst1 >= 0) {
            atomicAdd(acc + (size_t)dst1 * 64 + o,     av[nb][2] + g_y[(size_t)src1 * 64 + o]);
            atomicAdd(acc + (size_t)dst1 * 64 + o + 1, av[nb][3] + g_y[(size_t)src1 * 64 + o + 1]);
        }
    }
}

// ---------------- final MLP -------------------------------------------------
__global__ void __launch_bounds__(128)
mlp_kernel(const float* __restrict__ f1w, const float* __restrict__ f1b,
           const float* __restrict__ f2w, const float* __restrict__ f2b,
           const float* __restrict__ f3w, const float* __restrict__ f3b,
           float* __restrict__ out) {
    int g = blockIdx.x * blockDim.x + threadIdx.x;
    if (g >= NG) return;
    float inv = 1.f / fmaxf(g_cnt[g], 1.f);
    const float* sr = g_sums + g * 64;
    float h1[32];
#pragma unroll
    for (int j = 0; j < 32; j++) {
        float s = 0.f;
#pragma unroll
        for (int i = 0; i < 64; i++) s = fmaf(sr[i], f1w[i * 32 + j], s);
        h1[j] = eluf(fmaf(s, inv, f1b[j]));
    }
    float h2[16];
#pragma unroll
    for (int j = 0; j < 16; j++) {
        float s = f2b[j];
#pragma unroll
        for (int i = 0; i < 32; i++) s = fmaf(h1[i], f2w[i * 16 + j], s);
        h2[j] = eluf(s);
    }
    float s = f3b[0];
#pragma unroll
    for (int i = 0; i < 16; i++) s = fmaf(h2[i], f3w[i], s);
    out[g] = s;
}

// ---------------- driver ----------------------------------------------------
extern "C" void kernel_launch(void* const* d_in, const int* in_sizes, int n_in,
                              void* d_out, int out_size) {
    const float* x   = (const float*)d_in[0];
    const void*  ei  = d_in[1];
    const float* ea  = (const float*)d_in[2];
    const void*  bat = d_in[3];
    const float* W[24];
    for (int i = 0; i < 24; i++) W[i] = (const float*)d_in[4 + i];
    float* out = (float*)d_out;

    float *fa, *fb, *acc, *acc2;
    cudaGetSymbolAddress((void**)&fa, g_fa);
    cudaGetSymbolAddress((void**)&fb, g_fb);
    cudaGetSymbolAddress((void**)&acc, g_acc);
    cudaGetSymbolAddress((void**)&acc2, g_acc2);

    cudaFuncSetAttribute(msg_mma1_kernel,            cudaFuncAttributeMaxDynamicSharedMemorySize, SMEM2_BYTES);
    cudaFuncSetAttribute(msg_mma_kernel<32, 32, 7>,  cudaFuncAttributeMaxDynamicSharedMemorySize, SMEM_BYTES);
    cudaFuncSetAttribute(msg_mma_kernel<64, 64, 39>, cudaFuncAttributeMaxDynamicSharedMemorySize, SMEM_BYTES);

    // merged prep: convert + w2prep(all) + layer-1 rootxb2
    prep_kernel<<<PREP_B_CONV + PREP_B_W2 + PREP_B_ROOT, 256>>>(
        ei, bat, W[2], W[8], W[14], x, W[4], W[5], W[3], acc);

    // layer 1: 13 -> 32 (2 tiles per CTA)
    msg_mma1_kernel<<<(NTILES + 1) / 2, 256, SMEM2_BYTES>>>(x, acc, ea, W[0], W[1]);

    // transition 1->2, then layer 2
    trans_kernel<32><<<NN / 4, 256>>>(acc, fa, W[10], W[11], W[9], acc2);
    msg_mma_kernel<32, 32, 7><<<NTILES, 256, SMEM_BYTES>>>(fa, acc2, ea, W[6], W[7]);

    // transition 2->3, then layer 3
    trans_kernel<64><<<NN / 4, 256>>>(acc2, fb, W[16], W[17], W[15], acc);
    msg_mma_kernel<64, 64, 39><<<NTILES, 256, SMEM_BYTES>>>(fb, acc, ea, W[12], W[13]);

    // layer-3 elu + pooling, then head
    elu_pool_kernel<<<(NN + 31) / 32, 256>>>(acc);
    mlp_kernel<<<(NG + 127) / 128, 128>>>(W[18], W[19], W[20], W[21], W[22], W[23], out);
}

// round 14
// speedup vs baseline: 1.0108x; 1.0108x over previous
#include <cuda_runtime.h>
#include <cuda_fp16.h>
#include <math.h>
#include <stdint.h>

#define NE 50000
#define NN 25000
#define NG 1024
#define HID 128
#define NTILES 391

// msg smem (dynamic): A [128x272B] | B buf0|buf1|buf2 (64x272B each) | X16
#define SM_B      34816
#define SM_BUF    17408
#define SM_X      87040
#define SMEM_BYTES 103424

__device__ __align__(256) unsigned char g_w2s[103 * 16384];   // fp16 w2T chunks [64x256B]
__device__ float g_fa[NN * 64];
__device__ float g_fb[NN * 64];
__device__ float g_acc[NN * 64];
__device__ float g_acc2[NN * 64];
__device__ float g_y[NN * 64];        // x @ b2 per node
__device__ float g_sums[NG * 64];
__device__ float g_cnt[NG];
__device__ int g_src[NE], g_dst[NE], g_batch[NN];

__device__ __forceinline__ float eluf(float v) { return v > 0.f ? v : expm1f(v); }
__device__ __forceinline__ uint32_t s2u(const void* p) {
    uint32_t a;
    asm("{ .reg .u64 t; cvta.to.shared.u64 t, %1; cvt.u32.u64 %0, t; }" : "=r"(a) : "l"(p));
    return a;
}
__device__ __forceinline__ void cp16(uint32_t s, const void* g) {
    asm volatile("cp.async.cg.shared.global [%0], [%1], 16;" :: "r"(s), "l"(g));
}
__device__ __forceinline__ void cp_commit() { asm volatile("cp.async.commit_group;" ::: "memory"); }
template<int N> __device__ __forceinline__ void cp_wait() { asm volatile("cp.async.wait_group %0;" :: "n"(N) : "memory"); }
__device__ __forceinline__ void ldsm4(uint32_t* r, uint32_t a) {
    asm volatile("ldmatrix.sync.aligned.m8n8.x4.shared.b16 {%0,%1,%2,%3}, [%4];"
                 : "=r"(r[0]), "=r"(r[1]), "=r"(r[2]), "=r"(r[3]) : "r"(a));
}
__device__ __forceinline__ void mma16816(float* d, const uint32_t* a, uint32_t b0, uint32_t b1) {
    asm volatile("mma.sync.aligned.m16n8k16.row.col.f32.f16.f16.f32 "
                 "{%0,%1,%2,%3}, {%4,%5,%6,%7}, {%8,%9}, {%0,%1,%2,%3};"
                 : "+f"(d[0]), "+f"(d[1]), "+f"(d[2]), "+f"(d[3])
                 : "r"(a[0]), "r"(a[1]), "r"(a[2]), "r"(a[3]), "r"(b0), "r"(b1));
}

// ---------------- convert (detect inlined) + pool-zero ---------------------
__global__ void convert_kernel(const void* __restrict__ ei, const void* __restrict__ bat) {
    const long long* e64 = (const long long*)ei;
    int is64 = 1;
#pragma unroll
    for (int i = 0; i < 32; i++) {
        long long v = e64[i];
        if (v < 0 || v >= (long long)NN) { is64 = 0; break; }
    }
    int t = blockIdx.x * blockDim.x + threadIdx.x;
    if (t < NE) {
        if (is64) { g_src[t] = (int)((const long long*)ei)[t]; g_dst[t] = (int)((const long long*)ei)[NE + t]; }
        else      { g_src[t] = ((const int*)ei)[t];            g_dst[t] = ((const int*)ei)[NE + t]; }
    }
    if (t < NN) g_batch[t] = is64 ? (int)((const long long*)bat)[t] : ((const int*)bat)[t];
    if (t < NG * 64) g_sums[t] = 0.f;
    if (t < NG) g_cnt[t] = 0.f;
}

// -------- all 3 layers' w2 -> fp16 B chunk tiles (one launch) --------------
__global__ void w2prep_all_kernel(const float* __restrict__ w2a,
                                  const float* __restrict__ w2b,
                                  const float* __restrict__ w2c) {
    int t = blockIdx.x * blockDim.x + threadIdx.x;
    if (t >= 103 * 8192) return;
    int c = t >> 13, rem = t & 8191, r = rem >> 7, k = rem & 127;
    const float* w2; int cb, sz;
    if (c < 7)       { w2 = w2a; cb = 0;  sz = 13 * 32; }
    else if (c < 39) { w2 = w2b; cb = 7;  sz = 32 * 64; }
    else             { w2 = w2c; cb = 39; sz = 64 * 64; }
    int n = (c - cb) * 64 + r;
    float v = (n < sz) ? w2[k * sz + n] : 0.f;
    *(__half*)(g_w2s + (size_t)c * 16384 + r * 256 + k * 2) = __float2half(v);
}

// -------- layer-1 entry: acc = x @ root + bias; g_y = x @ b2 ---------------
template<int M_IN, int M_OUT>
__global__ void rootxb2_kernel(const float* __restrict__ x, const float* __restrict__ root,
                               const float* __restrict__ bias, const float* __restrict__ b2,
                               float* __restrict__ acc) {
    int t = blockIdx.x * blockDim.x + threadIdx.x;
    if (t >= NN * M_OUT) return;
    int n = t / M_OUT, o = t - n * M_OUT;
    const float* xr = x + n * M_IN;
    float s = bias[o], y = 0.f;
#pragma unroll
    for (int i = 0; i < M_IN; i++) {
        float xv = xr[i];
        s = fmaf(xv, root[i * M_OUT + o], s);
        y = fmaf(xv, b2[i * M_OUT + o], y);
    }
    acc[t] = s;
    g_y[t] = y;
}

// -------- layer transition: f = elu(acc_in); acc_out = f@root+bias; y = f@b2
template<int MI>
__global__ void __launch_bounds__(256)
trans_kernel(const float* __restrict__ acc_in, float* __restrict__ fout,
             const float* __restrict__ root, const float* __restrict__ bias,
             const float* __restrict__ b2, float* __restrict__ acc_out) {
    __shared__ float f[4][MI];
    const int tid = threadIdx.x;
    const int n0 = blockIdx.x * 4;
    if (tid < 4 * MI) {
        int n = tid / MI, i = tid - n * MI;
        float v = eluf(acc_in[(size_t)(n0 + n) * MI + i]);
        f[n][i] = v;
        fout[(size_t)(n0 + n) * MI + i] = v;
    }
    __syncthreads();
    const int n = tid >> 6, o = tid & 63;
    float s = bias[o], y = 0.f;
#pragma unroll
    for (int i = 0; i < MI; i++) {
        float fv = f[n][i];
        s = fmaf(fv, root[i * 64 + o], s);
        y = fmaf(fv, b2[i * 64 + o], y);
    }
    acc_out[(size_t)(n0 + n) * 64 + o] = s;
    g_y[(size_t)(n0 + n) * 64 + o] = y;
}

// -------- layer-3 elu + pooling with run-length aggregation ----------------
__global__ void __launch_bounds__(256)
elu_pool_kernel(const float* __restrict__ acc) {
    const int tid = threadIdx.x;
    const int o = tid & 63;
    const int grp = tid >> 6;
    const int n0 = blockIdx.x * 32 + grp * 8;
    float s = 0.f;
    int curg = -1;
    for (int j = 0; j < 8; j++) {
        const int n = n0 + j;
        if (n >= NN) break;
        const int g = g_batch[n];
        const float v = eluf(acc[(size_t)n * 64 + o]);
        if (g != curg) {
            if (curg >= 0) atomicAdd(&g_sums[curg * 64 + o], s);
            curg = g; s = v;
        } else s += v;
    }
    if (curg >= 0) atomicAdd(&g_sums[curg * 64 + o], s);
    if (o == 0) {
        float c = 0.f; int cg = -1;
        for (int j = 0; j < 8; j++) {
            const int n = n0 + j;
            if (n >= NN) break;
            const int g = g_batch[n];
            if (g != cg) { if (cg >= 0) atomicAdd(&g_cnt[cg], c); cg = g; c = 1.f; }
            else c += 1.f;
        }
        if (cg >= 0) atomicAdd(&g_cnt[cg], c);
    }
}

// -------- message GEMM: fused h prologue, 3-buffer B, smem-staged x --------
// New vs R12: for M_OUT=64 the per-chunk contraction scalars x[src_e, c] are
// pre-staged ONCE into smem as fp16, transposed x16[c][row]. Replaces ~8K
// scattered per-chunk LDG per CTA (the L1=66.5% hotspot in R13's profile)
// with 128 coalesced float4 row reads + conflict-free LDS.U16.
__device__ __forceinline__ void copyB(int cabs, uint32_t dst, int tid) {
    const unsigned char* gb = g_w2s + (size_t)cabs * 16384;
    for (int idx = tid; idx < 1024; idx += 256) {
        int r = idx >> 4, s = idx & 15;
        cp16(dst + r * 272 + s * 16, gb + r * 256 + s * 16);
    }
}

template<int M_IN, int M_OUT, int NC, int CBASE>
__global__ void __launch_bounds__(256, 2)
msg_mma_kernel(const float* __restrict__ xin, float* __restrict__ acc,
               const float* __restrict__ ea,
               const float* __restrict__ w1, const float* __restrict__ b1) {
    extern __shared__ char smem[];
    __shared__ float eas[640];
    const uint32_t sb = s2u(smem);
    const int tid = threadIdx.x, wid = tid >> 5, lane = tid & 31;
    const int tile = blockIdx.x;

    // kick off B copies first so they overlap the h compute + x staging
    copyB(CBASE, sb + SM_B, tid);
    cp_commit();
    if (NC > 1) { copyB(CBASE + 1, sb + SM_B + SM_BUF, tid); cp_commit(); }

    // stage ea slice
    {
        const int gbase = tile * 640;
        for (int idx = tid; idx < 640; idx += 256)
            eas[idx] = (gbase + idx < NE * 5) ? ea[gbase + idx] : 0.f;
    }

    // per-thread w1/b1 for its k-pair
    const int kp = tid & 63, k2 = kp * 2;
    float wv[10], bv0, bv1;
#pragma unroll
    for (int d = 0; d < 5; d++) {
        wv[2 * d]     = w1[d * HID + k2];
        wv[2 * d + 1] = w1[d * HID + k2 + 1];
    }
    bv0 = b1[k2]; bv1 = b1[k2 + 1];
    __syncthreads();                   // eas visible

    // compute h tile -> A smem (fp16 pairs)
    {
        const int rbase = tid >> 6;
        const int ecnt = min(128, NE - tile * 128);
#pragma unroll 8
        for (int j = 0; j < 32; j++) {
            const int r = rbase + 4 * j;
            uint32_t packed = 0;
            if (r < ecnt) {
                const float* a = eas + r * 5;
                float s0 = bv0, s1 = bv1;
                s0 = fmaf(a[0], wv[0], s0); s1 = fmaf(a[0], wv[1], s1);
                s0 = fmaf(a[1], wv[2], s0); s1 = fmaf(a[1], wv[3], s1);
                s0 = fmaf(a[2], wv[4], s0); s1 = fmaf(a[2], wv[5], s1);
                s0 = fmaf(a[3], wv[6], s0); s1 = fmaf(a[3], wv[7], s1);
                s0 = fmaf(a[4], wv[8], s0); s1 = fmaf(a[4], wv[9], s1);
                s0 = fmaxf(s0, 0.f); s1 = fmaxf(s1, 0.f);
                __half h0 = __float2half(s0), h1 = __float2half(s1);
                packed = ((uint32_t)__half_as_ushort(h1) << 16) | __half_as_ushort(h0);
            }
            *(uint32_t*)(smem + r * 272 + kp * 4) = packed;
        }
    }

    // stage x rows -> smem fp16 transposed x16[c][row] (M_OUT=64 layers only)
    if constexpr (M_OUT == 64) {
        const int r = tid >> 1;            // 0..127
        const int hh = tid & 1;            // which half of the row
        const int e = tile * 128 + r;
        const int srcr = (e < NE) ? g_src[e] : 0;
        const float4* xrow = (const float4*)(xin + (size_t)srcr * M_IN + hh * (M_IN / 2));
        __half* xs = (__half*)(smem + SM_X);
#pragma unroll
        for (int j = 0; j < M_IN / 8; j++) {
            float4 v = xrow[j];
            const int c0 = hh * (M_IN / 2) + j * 4;
            xs[(c0 + 0) * 128 + r] = __float2half(v.x);
            xs[(c0 + 1) * 128 + r] = __float2half(v.y);
            xs[(c0 + 2) * 128 + r] = __float2half(v.z);
            xs[(c0 + 3) * 128 + r] = __float2half(v.w);
        }
    }

    const int m0 = wid * 16;
    const int r0 = lane >> 2;
    const int e0 = tile * 128 + m0 + r0;
    const int e1 = e0 + 8;
    int src0 = 0, dst0 = -1, src1 = 0, dst1 = -1;
    if (e0 < NE) { src0 = g_src[e0]; dst0 = g_dst[e0]; }
    if (e1 < NE) { src1 = g_src[e1]; dst1 = g_dst[e1]; }

    const uint32_t lrow = (lane & 15);
    const uint32_t kh16 = (lane >> 4) * 16;
    const __half* xs = (const __half*)(smem + SM_X);

    float av[8][4];
#pragma unroll
    for (int nb = 0; nb < 8; nb++)
#pragma unroll
        for (int q = 0; q < 4; q++) av[nb][q] = 0.f;

    int bufc = 0;
    for (int c = 0; c < NC; c++) {
        if (c + 1 == NC) cp_wait<0>(); else cp_wait<1>();
        __syncthreads();               // chunk c's B + (c==0) A/X stores visible

        if (c + 2 < NC) {
            int b2i = bufc + 2; if (b2i >= 3) b2i -= 3;
            copyB(CBASE + c + 2, sb + SM_B + (uint32_t)b2i * SM_BUF, tid);
            cp_commit();
        }

        const uint32_t Bb = sb + SM_B + (uint32_t)bufc * SM_BUF;
        if (++bufc == 3) bufc = 0;
        float d[8][4];
#pragma unroll
        for (int nb = 0; nb < 8; nb++)
#pragma unroll
            for (int q = 0; q < 4; q++) d[nb][q] = 0.f;

#pragma unroll
        for (int ks = 0; ks < 8; ks++) {
            uint32_t a[4];
            ldsm4(a, sb + (m0 + lrow) * 272 + ks * 32 + kh16);
#pragma unroll
            for (int nb2 = 0; nb2 < 4; nb2++) {
                uint32_t b[4];
                ldsm4(b, Bb + (nb2 * 16 + lrow) * 272 + ks * 32 + kh16);
                mma16816(d[2 * nb2],     a, b[0], b[2]);
                mma16816(d[2 * nb2 + 1], a, b[1], b[3]);
            }
        }

        if constexpr (M_OUT == 64) {
            const float xs0 = __half2float(xs[c * 128 + m0 + r0]);
            const float xs1 = __half2float(xs[c * 128 + m0 + r0 + 8]);
#pragma unroll
            for (int nb = 0; nb < 8; nb++) {
                av[nb][0] = fmaf(xs0, d[nb][0], av[nb][0]);
                av[nb][1] = fmaf(xs0, d[nb][1], av[nb][1]);
                av[nb][2] = fmaf(xs1, d[nb][2], av[nb][2]);
                av[nb][3] = fmaf(xs1, d[nb][3], av[nb][3]);
            }
        } else {
            const int i0 = min(2 * c, M_IN - 1), i1 = min(2 * c + 1, M_IN - 1);
            const float x00 = xin[(size_t)src0 * M_IN + i0];
            const float x01 = xin[(size_t)src0 * M_IN + i1];
            const float x10 = xin[(size_t)src1 * M_IN + i0];
            const float x11 = xin[(size_t)src1 * M_IN + i1];
#pragma unroll
            for (int nb = 0; nb < 8; nb++) {
                const float xsa = (nb < 4) ? x00 : x01;
                const float xsb = (nb < 4) ? x10 : x11;
                av[nb][0] = fmaf(xsa, d[nb][0], av[nb][0]);
                av[nb][1] = fmaf(xsa, d[nb][1], av[nb][1]);
                av[nb][2] = fmaf(xsb, d[nb][2], av[nb][2]);
                av[nb][3] = fmaf(xsb, d[nb][3], av[nb][3]);
            }
        }
    }

    const int oc = (lane & 3) * 2;
    if constexpr (M_OUT == 64) {
#pragma unroll
        for (int nb = 0; nb < 8; nb++) {
            const int o = nb * 8 + oc;
            if (dst0 >= 0) {
                atomicAdd(acc + (size_t)dst0 * 64 + o,     av[nb][0] + g_y[(size_t)src0 * 64 + o]);
                atomicAdd(acc + (size_t)dst0 * 64 + o + 1, av[nb][1] + g_y[(size_t)src0 * 64 + o + 1]);
            }
            if (dst1 >= 0) {
                atomicAdd(acc + (size_t)dst1 * 64 + o,     av[nb][2] + g_y[(size_t)src1 * 64 + o]);
                atomicAdd(acc + (size_t)dst1 * 64 + o + 1, av[nb][3] + g_y[(size_t)src1 * 64 + o + 1]);
            }
        }
    } else {
#pragma unroll
        for (int nb = 0; nb < 4; nb++) {
            const int o = nb * 8 + oc;
            if (dst0 >= 0) {
                atomicAdd(acc + (size_t)dst0 * 32 + o,     av[nb][0] + av[nb + 4][0] + g_y[(size_t)src0 * 32 + o]);
                atomicAdd(acc + (size_t)dst0 * 32 + o + 1, av[nb][1] + av[nb + 4][1] + g_y[(size_t)src0 * 32 + o + 1]);
            }
            if (dst1 >= 0) {
                atomicAdd(acc + (size_t)dst1 * 32 + o,     av[nb][2] + av[nb + 4][2] + g_y[(size_t)src1 * 32 + o]);
                atomicAdd(acc + (size_t)dst1 * 32 + o + 1, av[nb][3] + av[nb + 4][3] + g_y[(size_t)src1 * 32 + o + 1]);
            }
        }
    }
}

// ---------------- final MLP -------------------------------------------------
__global__ void __launch_bounds__(128)
mlp_kernel(const float* __restrict__ f1w, const float* __restrict__ f1b,
           const float* __restrict__ f2w, const float* __restrict__ f2b,
           const float* __restrict__ f3w, const float* __restrict__ f3b,
           float* __restrict__ out) {
    int g = blockIdx.x * blockDim.x + threadIdx.x;
    if (g >= NG) return;
    float inv = 1.f / fmaxf(g_cnt[g], 1.f);
    const float* sr = g_sums + g * 64;
    float h1[32];
#pragma unroll
    for (int j = 0; j < 32; j++) {
        float s = 0.f;
#pragma unroll
        for (int i = 0; i < 64; i++) s = fmaf(sr[i], f1w[i * 32 + j], s);
        h1[j] = eluf(fmaf(s, inv, f1b[j]));
    }
    float h2[16];
#pragma unroll
    for (int j = 0; j < 16; j++) {
        float s = f2b[j];
#pragma unroll
        for (int i = 0; i < 32; i++) s = fmaf(h1[i], f2w[i * 16 + j], s);
        h2[j] = eluf(s);
    }
    float s = f3b[0];
#pragma unroll
    for (int i = 0; i < 16; i++) s = fmaf(h2[i], f3w[i], s);
    out[g] = s;
}

// ---------------- driver ----------------------------------------------------
extern "C" void kernel_launch(void* const* d_in, const int* in_sizes, int n_in,
                              void* d_out, int out_size) {
    const float* x   = (const float*)d_in[0];
    const void*  ei  = d_in[1];
    const float* ea  = (const float*)d_in[2];
    const void*  bat = d_in[3];
    const float* W[24];
    for (int i = 0; i < 24; i++) W[i] = (const float*)d_in[4 + i];
    float* out = (float*)d_out;

    float *fa, *fb, *acc, *acc2;
    cudaGetSymbolAddress((void**)&fa, g_fa);
    cudaGetSymbolAddress((void**)&fb, g_fb);
    cudaGetSymbolAddress((void**)&acc, g_acc);
    cudaGetSymbolAddress((void**)&acc2, g_acc2);

    cudaFuncSetAttribute(msg_mma_kernel<13, 32, 7, 0>,   cudaFuncAttributeMaxDynamicSharedMemorySize, SMEM_BYTES);
    cudaFuncSetAttribute(msg_mma_kernel<32, 64, 32, 7>,  cudaFuncAttributeMaxDynamicSharedMemorySize, SMEM_BYTES);
    cudaFuncSetAttribute(msg_mma_kernel<64, 64, 64, 39>, cudaFuncAttributeMaxDynamicSharedMemorySize, SMEM_BYTES);

    convert_kernel<<<(NG * 64 + 255) / 256, 256>>>(ei, bat);
    w2prep_all_kernel<<<(103 * 8192 + 255) / 256, 256>>>(W[2], W[8], W[14]);

    // layer 1: 13 -> 32
    rootxb2_kernel<13, 32><<<(NN * 32 + 255) / 256, 256>>>(x, W[4], W[5], W[3], acc);
    msg_mma_kernel<13, 32, 7, 0><<<NTILES, 256, SMEM_BYTES>>>(x, acc, ea, W[0], W[1]);

    // transition 1->2, then layer 2
    trans_kernel<32><<<NN / 4, 256>>>(acc, fa, W[10], W[11], W[9], acc2);
    msg_mma_kernel<32, 64, 32, 7><<<NTILES, 256, SMEM_BYTES>>>(fa, acc2, ea, W[6], W[7]);

    // transition 2->3, then layer 3
    trans_kernel<64><<<NN / 4, 256>>>(acc2, fb, W[16], W[17], W[15], acc);
    msg_mma_kernel<64, 64, 64, 39><<<NTILES, 256, SMEM_BYTES>>>(fb, acc, ea, W[12], W[13]);

    // layer-3 elu + pooling, then head
    elu_pool_kernel<<<(NN + 31) / 32, 256>>>(acc);
    mlp_kernel<<<(NG + 127) / 128, 128>>>(W[18], W[19], W[20], W[21], W[22], W[23], out);
}

// round 15
// speedup vs baseline: 1.0158x; 1.0049x over previous
#include <cuda_runtime.h>
#include <cuda_fp16.h>
#include <math.h>
#include <stdint.h>

#define NE 50000
#define NN 25000
#define NG 1024
#define HID 128
#define NTILES 391

// msg smem (dynamic): A [128x272B] | B buf0|buf1|buf2 (64x272B each) | X16
#define SM_B      34816
#define SM_BUF    17408
#define SM_X      87040
#define SMEM_BYTES 103424

__device__ __align__(256) unsigned char g_w2s[103 * 16384];   // fp16 w2T chunks [64x256B]
__device__ float g_acc[NN * 64];
__device__ float g_acc2[NN * 64];
__device__ float g_y[NN * 64];        // f @ b2 per node
__device__ float g_sums[NG * 64];
__device__ float g_cnt[NG];
__device__ int g_src[NE], g_dst[NE], g_batch[NN];

__device__ __forceinline__ float eluf(float v) { return v > 0.f ? v : expm1f(v); }
__device__ __forceinline__ uint32_t s2u(const void* p) {
    uint32_t a;
    asm("{ .reg .u64 t; cvta.to.shared.u64 t, %1; cvt.u32.u64 %0, t; }" : "=r"(a) : "l"(p));
    return a;
}
__device__ __forceinline__ void cp16(uint32_t s, const void* g) {
    asm volatile("cp.async.cg.shared.global [%0], [%1], 16;" :: "r"(s), "l"(g));
}
__device__ __forceinline__ void cp_commit() { asm volatile("cp.async.commit_group;" ::: "memory"); }
template<int N> __device__ __forceinline__ void cp_wait() { asm volatile("cp.async.wait_group %0;" :: "n"(N) : "memory"); }
__device__ __forceinline__ void ldsm4(uint32_t* r, uint32_t a) {
    asm volatile("ldmatrix.sync.aligned.m8n8.x4.shared.b16 {%0,%1,%2,%3}, [%4];"
                 : "=r"(r[0]), "=r"(r[1]), "=r"(r[2]), "=r"(r[3]) : "r"(a));
}
__device__ __forceinline__ void mma16816(float* d, const uint32_t* a, uint32_t b0, uint32_t b1) {
    asm volatile("mma.sync.aligned.m16n8k16.row.col.f32.f16.f16.f32 "
                 "{%0,%1,%2,%3}, {%4,%5,%6,%7}, {%8,%9}, {%0,%1,%2,%3};"
                 : "+f"(d[0]), "+f"(d[1]), "+f"(d[2]), "+f"(d[3])
                 : "r"(a[0]), "r"(a[1]), "r"(a[2]), "r"(a[3]), "r"(b0), "r"(b1));
}

// ---------------- merged prep: convert + w2prep + layer-1 rootxb2 ----------
#define PREP_B_CONV 256          // convert + pool-zero
#define PREP_B_W2   3296         // w2 chunk tiles (103*8192 threads)
#define PREP_B_ROOT 3125         // rootxb2<13,32> (NN*32 threads)
__global__ void prep_kernel(const void* __restrict__ ei, const void* __restrict__ bat,
                            const float* __restrict__ w2a, const float* __restrict__ w2b,
                            const float* __restrict__ w2c,
                            const float* __restrict__ x, const float* __restrict__ root,
                            const float* __restrict__ bias, const float* __restrict__ b2,
                            float* __restrict__ acc) {
    const int b = blockIdx.x;
    if (b < PREP_B_CONV) {
        const long long* e64 = (const long long*)ei;
        int is64 = 1;
#pragma unroll
        for (int i = 0; i < 32; i++) {
            long long v = e64[i];
            if (v < 0 || v >= (long long)NN) { is64 = 0; break; }
        }
        int t = b * 256 + threadIdx.x;
        if (t < NE) {
            if (is64) { g_src[t] = (int)((const long long*)ei)[t]; g_dst[t] = (int)((const long long*)ei)[NE + t]; }
            else      { g_src[t] = ((const int*)ei)[t];            g_dst[t] = ((const int*)ei)[NE + t]; }
        }
        if (t < NN) g_batch[t] = is64 ? (int)((const long long*)bat)[t] : ((const int*)bat)[t];
        if (t < NG * 64) g_sums[t] = 0.f;
        if (t < NG) g_cnt[t] = 0.f;
    } else if (b < PREP_B_CONV + PREP_B_W2) {
        int t = (b - PREP_B_CONV) * 256 + threadIdx.x;
        if (t >= 103 * 8192) return;
        int c = t >> 13, rem = t & 8191, r = rem >> 7, k = rem & 127;
        const float* w2; int cb, sz;
        if (c < 7)       { w2 = w2a; cb = 0;  sz = 13 * 32; }
        else if (c < 39) { w2 = w2b; cb = 7;  sz = 32 * 64; }
        else             { w2 = w2c; cb = 39; sz = 64 * 64; }
        int n = (c - cb) * 64 + r;
        float v = (n < sz) ? w2[k * sz + n] : 0.f;
        *(__half*)(g_w2s + (size_t)c * 16384 + r * 256 + k * 2) = __float2half(v);
    } else {
        int t = (b - PREP_B_CONV - PREP_B_W2) * 256 + threadIdx.x;
        if (t >= NN * 32) return;
        int n = t >> 5, o = t & 31;
        const float* xr = x + n * 13;
        float s = bias[o], y = 0.f;
#pragma unroll
        for (int i = 0; i < 13; i++) {
            float xv = xr[i];
            s = fmaf(xv, root[i * 32 + o], s);
            y = fmaf(xv, b2[i * 32 + o], y);
        }
        acc[t] = s;
        g_y[t] = y;
    }
}

// -------- layer transition: acc_out = elu(acc_in)@root+bias; y = elu@b2 ----
// No materialized feature buffer: the next msg kernel recomputes elu(acc_in)
// during its x-staging (bitwise identical), so fout is gone entirely.
template<int MI>
__global__ void __launch_bounds__(256)
trans_kernel(const float* __restrict__ acc_in,
             const float* __restrict__ root, const float* __restrict__ bias,
             const float* __restrict__ b2, float* __restrict__ acc_out) {
    __shared__ float f[4][MI];
    const int tid = threadIdx.x;
    const int n0 = blockIdx.x * 4;
    if (tid < 4 * MI) {
        int n = tid / MI, i = tid - n * MI;
        f[n][i] = eluf(acc_in[(size_t)(n0 + n) * MI + i]);
    }
    __syncthreads();
    const int n = tid >> 6, o = tid & 63;
    float s = bias[o], y = 0.f;
#pragma unroll
    for (int i = 0; i < MI; i++) {
        float fv = f[n][i];
        s = fmaf(fv, root[i * 64 + o], s);
        y = fmaf(fv, b2[i * 64 + o], y);
    }
    acc_out[(size_t)(n0 + n) * 64 + o] = s;
    g_y[(size_t)(n0 + n) * 64 + o] = y;
}

// -------- layer-3 elu + pooling with run-length aggregation ----------------
__global__ void __launch_bounds__(256)
elu_pool_kernel(const float* __restrict__ acc) {
    const int tid = threadIdx.x;
    const int o = tid & 63;
    const int grp = tid >> 6;
    const int n0 = blockIdx.x * 32 + grp * 8;
    float s = 0.f;
    int curg = -1;
    for (int j = 0; j < 8; j++) {
        const int n = n0 + j;
        if (n >= NN) break;
        const int g = g_batch[n];
        const float v = eluf(acc[(size_t)n * 64 + o]);
        if (g != curg) {
            if (curg >= 0) atomicAdd(&g_sums[curg * 64 + o], s);
            curg = g; s = v;
        } else s += v;
    }
    if (curg >= 0) atomicAdd(&g_sums[curg * 64 + o], s);
    if (o == 0) {
        float c = 0.f; int cg = -1;
        for (int j = 0; j < 8; j++) {
            const int n = n0 + j;
            if (n >= NN) break;
            const int g = g_batch[n];
            if (g != cg) { if (cg >= 0) atomicAdd(&g_cnt[cg], c); cg = g; c = 1.f; }
            else c += 1.f;
        }
        if (cg >= 0) atomicAdd(&g_cnt[cg], c);
    }
}

// -------- message GEMM: fused h prologue, 3-buffer B, elu-fused x staging --
// M_OUT=64 layers read the RAW accumulator of the previous layer and apply
// elu during fp16 x-staging (features never materialized in global memory).
__device__ __forceinline__ void copyB(int cabs, uint32_t dst, int tid) {
    const unsigned char* gb = g_w2s + (size_t)cabs * 16384;
    for (int idx = tid; idx < 1024; idx += 256) {
        int r = idx >> 4, s = idx & 15;
        cp16(dst + r * 272 + s * 16, gb + r * 256 + s * 16);
    }
}

template<int M_IN, int M_OUT, int NC, int CBASE, int DO_ELU>
__global__ void __launch_bounds__(256, 2)
msg_mma_kernel(const float* __restrict__ xin, float* __restrict__ acc,
               const float* __restrict__ ea,
               const float* __restrict__ w1, const float* __restrict__ b1) {
    extern __shared__ char smem[];
    __shared__ float eas[640];
    const uint32_t sb = s2u(smem);
    const int tid = threadIdx.x, wid = tid >> 5, lane = tid & 31;
    const int tile = blockIdx.x;

    copyB(CBASE, sb + SM_B, tid);
    cp_commit();
    if (NC > 1) { copyB(CBASE + 1, sb + SM_B + SM_BUF, tid); cp_commit(); }

    {
        const int gbase = tile * 640;
        for (int idx = tid; idx < 640; idx += 256)
            eas[idx] = (gbase + idx < NE * 5) ? ea[gbase + idx] : 0.f;
    }

    const int kp = tid & 63, k2 = kp * 2;
    float wv[10], bv0, bv1;
#pragma unroll
    for (int d = 0; d < 5; d++) {
        wv[2 * d]     = w1[d * HID + k2];
        wv[2 * d + 1] = w1[d * HID + k2 + 1];
    }
    bv0 = b1[k2]; bv1 = b1[k2 + 1];
    __syncthreads();

    // h tile -> A smem (fp16 pairs)
    {
        const int rbase = tid >> 6;
        const int ecnt = min(128, NE - tile * 128);
#pragma unroll 8
        for (int j = 0; j < 32; j++) {
            const int r = rbase + 4 * j;
            uint32_t packed = 0;
            if (r < ecnt) {
                const float* a = eas + r * 5;
                float s0 = bv0, s1 = bv1;
                s0 = fmaf(a[0], wv[0], s0); s1 = fmaf(a[0], wv[1], s1);
                s0 = fmaf(a[1], wv[2], s0); s1 = fmaf(a[1], wv[3], s1);
                s0 = fmaf(a[2], wv[4], s0); s1 = fmaf(a[2], wv[5], s1);
                s0 = fmaf(a[3], wv[6], s0); s1 = fmaf(a[3], wv[7], s1);
                s0 = fmaf(a[4], wv[8], s0); s1 = fmaf(a[4], wv[9], s1);
                s0 = fmaxf(s0, 0.f); s1 = fmaxf(s1, 0.f);
                __half h0 = __float2half(s0), h1 = __float2half(s1);
                packed = ((uint32_t)__half_as_ushort(h1) << 16) | __half_as_ushort(h0);
            }
            *(uint32_t*)(smem + r * 272 + kp * 4) = packed;
        }
    }

    // x rows -> smem fp16 transposed x16[c][row]; elu applied when DO_ELU
    if constexpr (M_OUT == 64) {
        const int r = tid >> 1;
        const int hh = tid & 1;
        const int e = tile * 128 + r;
        const int srcr = (e < NE) ? g_src[e] : 0;
        const float4* xrow = (const float4*)(xin + (size_t)srcr * M_IN + hh * (M_IN / 2));
        __half* xs = (__half*)(smem + SM_X);
#pragma unroll
        for (int j = 0; j < M_IN / 8; j++) {
            float4 v = xrow[j];
            if (DO_ELU) { v.x = eluf(v.x); v.y = eluf(v.y); v.z = eluf(v.z); v.w = eluf(v.w); }
            const int c0 = hh * (M_IN / 2) + j * 4;
            xs[(c0 + 0) * 128 + r] = __float2half(v.x);
            xs[(c0 + 1) * 128 + r] = __float2half(v.y);
            xs[(c0 + 2) * 128 + r] = __float2half(v.z);
            xs[(c0 + 3) * 128 + r] = __float2half(v.w);
        }
    }

    const int m0 = wid * 16;
    const int r0 = lane >> 2;
    const int e0 = tile * 128 + m0 + r0;
    const int e1 = e0 + 8;
    int src0 = 0, dst0 = -1, src1 = 0, dst1 = -1;
    if (e0 < NE) { src0 = g_src[e0]; dst0 = g_dst[e0]; }
    if (e1 < NE) { src1 = g_src[e1]; dst1 = g_dst[e1]; }

    const uint32_t lrow = (lane & 15);
    const uint32_t kh16 = (lane >> 4) * 16;
    const __half* xs = (const __half*)(smem + SM_X);

    float av[8][4];
#pragma unroll
    for (int nb = 0; nb < 8; nb++)
#pragma unroll
        for (int q = 0; q < 4; q++) av[nb][q] = 0.f;

    int bufc = 0;
    for (int c = 0; c < NC; c++) {
        if (c + 1 == NC) cp_wait<0>(); else cp_wait<1>();
        __syncthreads();

        if (c + 2 < NC) {
            int b2i = bufc + 2; if (b2i >= 3) b2i -= 3;
            copyB(CBASE + c + 2, sb + SM_B + (uint32_t)b2i * SM_BUF, tid);
            cp_commit();
        }

        const uint32_t Bb = sb + SM_B + (uint32_t)bufc * SM_BUF;
        if (++bufc == 3) bufc = 0;
        float d[8][4];
#pragma unroll
        for (int nb = 0; nb < 8; nb++)
#pragma unroll
            for (int q = 0; q < 4; q++) d[nb][q] = 0.f;

#pragma unroll
        for (int ks = 0; ks < 8; ks++) {
            uint32_t a[4];
            ldsm4(a, sb + (m0 + lrow) * 272 + ks * 32 + kh16);
#pragma unroll
            for (int nb2 = 0; nb2 < 4; nb2++) {
                uint32_t b[4];
                ldsm4(b, Bb + (nb2 * 16 + lrow) * 272 + ks * 32 + kh16);
                mma16816(d[2 * nb2],     a, b[0], b[2]);
                mma16816(d[2 * nb2 + 1], a, b[1], b[3]);
            }
        }

        if constexpr (M_OUT == 64) {
            const float xs0 = __half2float(xs[c * 128 + m0 + r0]);
            const float xs1 = __half2float(xs[c * 128 + m0 + r0 + 8]);
#pragma unroll
            for (int nb = 0; nb < 8; nb++) {
                av[nb][0] = fmaf(xs0, d[nb][0], av[nb][0]);
                av[nb][1] = fmaf(xs0, d[nb][1], av[nb][1]);
                av[nb][2] = fmaf(xs1, d[nb][2], av[nb][2]);
                av[nb][3] = fmaf(xs1, d[nb][3], av[nb][3]);
            }
        } else {
            const int i0 = min(2 * c, M_IN - 1), i1 = min(2 * c + 1, M_IN - 1);
            const float x00 = xin[(size_t)src0 * M_IN + i0];
            const float x01 = xin[(size_t)src0 * M_IN + i1];
            const float x10 = xin[(size_t)src1 * M_IN + i0];
            const float x11 = xin[(size_t)src1 * M_IN + i1];
#pragma unroll
            for (int nb = 0; nb < 8; nb++) {
                const float xsa = (nb < 4) ? x00 : x01;
                const float xsb = (nb < 4) ? x10 : x11;
                av[nb][0] = fmaf(xsa, d[nb][0], av[nb][0]);
                av[nb][1] = fmaf(xsa, d[nb][1], av[nb][1]);
                av[nb][2] = fmaf(xsb, d[nb][2], av[nb][2]);
                av[nb][3] = fmaf(xsb, d[nb][3], av[nb][3]);
            }
        }
    }

    const int oc = (lane & 3) * 2;
    if constexpr (M_OUT == 64) {
#pragma unroll
        for (int nb = 0; nb < 8; nb++) {
            const int o = nb * 8 + oc;
            if (dst0 >= 0) {
                atomicAdd(acc + (size_t)dst0 * 64 + o,     av[nb][0] + g_y[(size_t)src0 * 64 + o]);
                atomicAdd(acc + (size_t)dst0 * 64 + o + 1, av[nb][1] + g_y[(size_t)src0 * 64 + o + 1]);
            }
            if (dst1 >= 0) {
                atomicAdd(acc + (size_t)dst1 * 64 + o,     av[nb][2] + g_y[(size_t)src1 * 64 + o]);
                atomicAdd(acc + (size_t)dst1 * 64 + o + 1, av[nb][3] + g_y[(size_t)src1 * 64 + o + 1]);
            }
        }
    } else {
#pragma unroll
        for (int nb = 0; nb < 4; nb++) {
            const int o = nb * 8 + oc;
            if (dst0 >= 0) {
                atomicAdd(acc + (size_t)dst0 * 32 + o,     av[nb][0] + av[nb + 4][0] + g_y[(size_t)src0 * 32 + o]);
                atomicAdd(acc + (size_t)dst0 * 32 + o + 1, av[nb][1] + av[nb + 4][1] + g_y[(size_t)src0 * 32 + o + 1]);
            }
            if (dst1 >= 0) {
                atomicAdd(acc + (size_t)dst1 * 32 + o,     av[nb][2] + av[nb + 4][2] + g_y[(size_t)src1 * 32 + o]);
                atomicAdd(acc + (size_t)dst1 * 32 + o + 1, av[nb][3] + av[nb + 4][3] + g_y[(size_t)src1 * 32 + o + 1]);
            }
        }
    }
}

// ---------------- final MLP -------------------------------------------------
__global__ void __launch_bounds__(128)
mlp_kernel(const float* __restrict__ f1w, const float* __restrict__ f1b,
           const float* __restrict__ f2w, const float* __restrict__ f2b,
           const float* __restrict__ f3w, const float* __restrict__ f3b,
           float* __restrict__ out) {
    int g = blockIdx.x * blockDim.x + threadIdx.x;
    if (g >= NG) return;
    float inv = 1.f / fmaxf(g_cnt[g], 1.f);
    const float* sr = g_sums + g * 64;
    float h1[32];
#pragma unroll
    for (int j = 0; j < 32; j++) {
        float s = 0.f;
#pragma unroll
        for (int i = 0; i < 64; i++) s = fmaf(sr[i], f1w[i * 32 + j], s);
        h1[j] = eluf(fmaf(s, inv, f1b[j]));
    }
    float h2[16];
#pragma unroll
    for (int j = 0; j < 16; j++) {
        float s = f2b[j];
#pragma unroll
        for (int i = 0; i < 32; i++) s = fmaf(h1[i], f2w[i * 16 + j], s);
        h2[j] = eluf(s);
    }
    float s = f3b[0];
#pragma unroll
    for (int i = 0; i < 16; i++) s = fmaf(h2[i], f3w[i], s);
    out[g] = s;
}

// ---------------- driver ----------------------------------------------------
extern "C" void kernel_launch(void* const* d_in, const int* in_sizes, int n_in,
                              void* d_out, int out_size) {
    const float* x   = (const float*)d_in[0];
    const void*  ei  = d_in[1];
    const float* ea  = (const float*)d_in[2];
    const void*  bat = d_in[3];
    const float* W[24];
    for (int i = 0; i < 24; i++) W[i] = (const float*)d_in[4 + i];
    float* out = (float*)d_out;

    float *acc, *acc2;
    cudaGetSymbolAddress((void**)&acc, g_acc);
    cudaGetSymbolAddress((void**)&acc2, g_acc2);

    cudaFuncSetAttribute(msg_mma_kernel<13, 32, 7, 0, 0>,   cudaFuncAttributeMaxDynamicSharedMemorySize, SMEM_BYTES);
    cudaFuncSetAttribute(msg_mma_kernel<32, 64, 32, 7, 1>,  cudaFuncAttributeMaxDynamicSharedMemorySize, SMEM_BYTES);
    cudaFuncSetAttribute(msg_mma_kernel<64, 64, 64, 39, 1>, cudaFuncAttributeMaxDynamicSharedMemorySize, SMEM_BYTES);

    // merged prep: convert + pool-zero + w2prep(all) + layer-1 rootxb2
    prep_kernel<<<PREP_B_CONV + PREP_B_W2 + PREP_B_ROOT, 256>>>(
        ei, bat, W[2], W[8], W[14], x, W[4], W[5], W[3], acc);

    // layer 1: 13 -> 32 (x is the raw input; no elu)
    msg_mma_kernel<13, 32, 7, 0, 0><<<NTILES, 256, SMEM_BYTES>>>(x, acc, ea, W[0], W[1]);

    // transition 1->2 (root/b2 only), then layer 2 (elu fused into x staging)
    trans_kernel<32><<<NN / 4, 256>>>(acc, W[10], W[11], W[9], acc2);
    msg_mma_kernel<32, 64, 32, 7, 1><<<NTILES, 256, SMEM_BYTES>>>(acc, acc2, ea, W[6], W[7]);

    // transition 2->3, then layer 3
    trans_kernel<64><<<NN / 4, 256>>>(acc2, W[16], W[17], W[15], acc);
    msg_mma_kernel<64, 64, 64, 39, 1><<<NTILES, 256, SMEM_BYTES>>>(acc2, acc, ea, W[12], W[13]);

    // layer-3 elu + pooling, then head
    elu_pool_kernel<<<(NN + 31) / 32, 256>>>(acc);
    mlp_kernel<<<(NG + 127) / 128, 128>>>(W[18], W[19], W[20], W[21], W[22], W[23], out);
}

// round 16
// speedup vs baseline: 1.0635x; 1.0470x over previous
#include <cuda_runtime.h>
#include <cuda_fp16.h>
#include <math.h>
#include <stdint.h>

#define NE 50000
#define NN 25000
#define NG 1024
#define HID 128
#define NTILES 391

// msg smem (dynamic): A [128x272B] | B buf0|buf1|buf2 (64x272B each) | X16
#define SM_B      34816
#define SM_BUF    17408
#define SM_X      87040
#define SMEM_BYTES 103424

__device__ __align__(256) unsigned char g_w2s[103 * 16384];   // fp16 w2T chunks [64x256B]
__device__ float g_acc[NN * 64];
__device__ float g_acc2[NN * 64];
__device__ float g_y[NN * 64];        // f @ b2 per node
__device__ float g_sums[NG * 64];
__device__ float g_cnt[NG];
__device__ int g_src[NE], g_dst[NE], g_batch[NN];

__device__ __forceinline__ float eluf(float v) { return v > 0.f ? v : expm1f(v); }
__device__ __forceinline__ uint32_t s2u(const void* p) {
    uint32_t a;
    asm("{ .reg .u64 t; cvta.to.shared.u64 t, %1; cvt.u32.u64 %0, t; }" : "=r"(a) : "l"(p));
    return a;
}
__device__ __forceinline__ void cp16(uint32_t s, const void* g) {
    asm volatile("cp.async.cg.shared.global [%0], [%1], 16;" :: "r"(s), "l"(g));
}
__device__ __forceinline__ void cp_commit() { asm volatile("cp.async.commit_group;" ::: "memory"); }
template<int N> __device__ __forceinline__ void cp_wait() { asm volatile("cp.async.wait_group %0;" :: "n"(N) : "memory"); }
__device__ __forceinline__ void ldsm4(uint32_t* r, uint32_t a) {
    asm volatile("ldmatrix.sync.aligned.m8n8.x4.shared.b16 {%0,%1,%2,%3}, [%4];"
                 : "=r"(r[0]), "=r"(r[1]), "=r"(r[2]), "=r"(r[3]) : "r"(a));
}
__device__ __forceinline__ void mma16816(float* d, const uint32_t* a, uint32_t b0, uint32_t b1) {
    asm volatile("mma.sync.aligned.m16n8k16.row.col.f32.f16.f16.f32 "
                 "{%0,%1,%2,%3}, {%4,%5,%6,%7}, {%8,%9}, {%0,%1,%2,%3};"
                 : "+f"(d[0]), "+f"(d[1]), "+f"(d[2]), "+f"(d[3])
                 : "r"(a[0]), "r"(a[1]), "r"(a[2]), "r"(a[3]), "r"(b0), "r"(b1));
}

// ---------------- merged prep: convert + w2prep + layer-1 rootxb2 ----------
#define PREP_B_CONV 256
#define PREP_B_W2   3296
#define PREP_B_ROOT 3125
__global__ void prep_kernel(const void* __restrict__ ei, const void* __restrict__ bat,
                            const float* __restrict__ w2a, const float* __restrict__ w2b,
                            const float* __restrict__ w2c,
                            const float* __restrict__ x, const float* __restrict__ root,
                            const float* __restrict__ bias, const float* __restrict__ b2,
                            float* __restrict__ acc) {
    const int b = blockIdx.x;
    if (b < PREP_B_CONV) {
        const long long* e64 = (const long long*)ei;
        int is64 = 1;
#pragma unroll
        for (int i = 0; i < 32; i++) {
            long long v = e64[i];
            if (v < 0 || v >= (long long)NN) { is64 = 0; break; }
        }
        int t = b * 256 + threadIdx.x;
        if (t < NE) {
            if (is64) { g_src[t] = (int)((const long long*)ei)[t]; g_dst[t] = (int)((const long long*)ei)[NE + t]; }
            else      { g_src[t] = ((const int*)ei)[t];            g_dst[t] = ((const int*)ei)[NE + t]; }
        }
        if (t < NN) g_batch[t] = is64 ? (int)((const long long*)bat)[t] : ((const int*)bat)[t];
        if (t < NG * 64) g_sums[t] = 0.f;
        if (t < NG) g_cnt[t] = 0.f;
    } else if (b < PREP_B_CONV + PREP_B_W2) {
        int t = (b - PREP_B_CONV) * 256 + threadIdx.x;
        if (t >= 103 * 8192) return;
        int c = t >> 13, rem = t & 8191, r = rem >> 7, k = rem & 127;
        const float* w2; int cb, sz;
        if (c < 7)       { w2 = w2a; cb = 0;  sz = 13 * 32; }
        else if (c < 39) { w2 = w2b; cb = 7;  sz = 32 * 64; }
        else             { w2 = w2c; cb = 39; sz = 64 * 64; }
        int n = (c - cb) * 64 + r;
        float v = (n < sz) ? w2[k * sz + n] : 0.f;
        *(__half*)(g_w2s + (size_t)c * 16384 + r * 256 + k * 2) = __float2half(v);
    } else {
        int t = (b - PREP_B_CONV - PREP_B_W2) * 256 + threadIdx.x;
        if (t >= NN * 32) return;
        int n = t >> 5, o = t & 31;
        const float* xr = x + n * 13;
        float s = bias[o], y = 0.f;
#pragma unroll
        for (int i = 0; i < 13; i++) {
            float xv = xr[i];
            s = fmaf(xv, root[i * 32 + o], s);
            y = fmaf(xv, b2[i * 32 + o], y);
        }
        acc[t] = s;
        g_y[t] = y;
    }
}

// -------- layer transition: acc_out = elu(acc_in)@root+bias; y = elu@b2 ----
template<int MI>
__global__ void __launch_bounds__(256)
trans_kernel(const float* __restrict__ acc_in,
             const float* __restrict__ root, const float* __restrict__ bias,
             const float* __restrict__ b2, float* __restrict__ acc_out) {
    __shared__ float f[4][MI];
    const int tid = threadIdx.x;
    const int n0 = blockIdx.x * 4;
    if (tid < 4 * MI) {
        int n = tid / MI, i = tid - n * MI;
        f[n][i] = eluf(acc_in[(size_t)(n0 + n) * MI + i]);
    }
    __syncthreads();
    const int n = tid >> 6, o = tid & 63;
    float s = bias[o], y = 0.f;
#pragma unroll
    for (int i = 0; i < MI; i++) {
        float fv = f[n][i];
        s = fmaf(fv, root[i * 64 + o], s);
        y = fmaf(fv, b2[i * 64 + o], y);
    }
    acc_out[(size_t)(n0 + n) * 64 + o] = s;
    g_y[(size_t)(n0 + n) * 64 + o] = y;
}

// -------- layer-3 elu + pooling with run-length aggregation ----------------
__global__ void __launch_bounds__(256)
elu_pool_kernel(const float* __restrict__ acc) {
    const int tid = threadIdx.x;
    const int o = tid & 63;
    const int grp = tid >> 6;
    const int n0 = blockIdx.x * 32 + grp * 8;
    float s = 0.f;
    int curg = -1;
    for (int j = 0; j < 8; j++) {
        const int n = n0 + j;
        if (n >= NN) break;
        const int g = g_batch[n];
        const float v = eluf(acc[(size_t)n * 64 + o]);
        if (g != curg) {
            if (curg >= 0) atomicAdd(&g_sums[curg * 64 + o], s);
            curg = g; s = v;
        } else s += v;
    }
    if (curg >= 0) atomicAdd(&g_sums[curg * 64 + o], s);
    if (o == 0) {
        float c = 0.f; int cg = -1;
        for (int j = 0; j < 8; j++) {
            const int n = n0 + j;
            if (n >= NN) break;
            const int g = g_batch[n];
            if (g != cg) { if (cg >= 0) atomicAdd(&g_cnt[cg], c); cg = g; c = 1.f; }
            else c += 1.f;
        }
        if (cg >= 0) atomicAdd(&g_cnt[cg], c);
    }
}

__device__ __forceinline__ void copyB(int cabs, uint32_t dst, int tid) {
    const unsigned char* gb = g_w2s + (size_t)cabs * 16384;
    for (int idx = tid; idx < 1024; idx += 256) {
        int r = idx >> 4, s = idx & 15;
        cp16(dst + r * 272 + s * 16, gb + r * 256 + s * 16);
    }
}

// shared prologue: h tile + ea staging (identical to R15)
template<int NC, int CBASE>
__device__ __forceinline__ void msg_prologue(uint32_t sb, char* smem, float* eas,
                                             const float* ea, const float* w1,
                                             const float* b1, int tile, int tid) {
    copyB(CBASE, sb + SM_B, tid);
    cp_commit();
    if (NC > 1) { copyB(CBASE + 1, sb + SM_B + SM_BUF, tid); cp_commit(); }
    {
        const int gbase = tile * 640;
        for (int idx = tid; idx < 640; idx += 256)
            eas[idx] = (gbase + idx < NE * 5) ? ea[gbase + idx] : 0.f;
    }
    const int kp = tid & 63, k2 = kp * 2;
    float wv[10], bv0, bv1;
#pragma unroll
    for (int d = 0; d < 5; d++) {
        wv[2 * d]     = w1[d * HID + k2];
        wv[2 * d + 1] = w1[d * HID + k2 + 1];
    }
    bv0 = b1[k2]; bv1 = b1[k2 + 1];
    __syncthreads();
    {
        const int rbase = tid >> 6;
        const int ecnt = min(128, NE - tile * 128);
#pragma unroll 8
        for (int j = 0; j < 32; j++) {
            const int r = rbase + 4 * j;
            uint32_t packed = 0;
            if (r < ecnt) {
                const float* a = eas + r * 5;
                float s0 = bv0, s1 = bv1;
                s0 = fmaf(a[0], wv[0], s0); s1 = fmaf(a[0], wv[1], s1);
                s0 = fmaf(a[1], wv[2], s0); s1 = fmaf(a[1], wv[3], s1);
                s0 = fmaf(a[2], wv[4], s0); s1 = fmaf(a[2], wv[5], s1);
                s0 = fmaf(a[3], wv[6], s0); s1 = fmaf(a[3], wv[7], s1);
                s0 = fmaf(a[4], wv[8], s0); s1 = fmaf(a[4], wv[9], s1);
                s0 = fmaxf(s0, 0.f); s1 = fmaxf(s1, 0.f);
                __half h0 = __float2half(s0), h1 = __float2half(s1);
                packed = ((uint32_t)__half_as_ushort(h1) << 16) | __half_as_ushort(h0);
            }
            *(uint32_t*)(smem + r * 272 + kp * 4) = packed;
        }
    }
}

// -------- LAYER-1 msg (R15 shape, M_OUT=32, unchanged) ---------------------
__global__ void __launch_bounds__(256, 2)
msg_mma1_kernel(const float* __restrict__ xin, float* __restrict__ acc,
                const float* __restrict__ ea,
                const float* __restrict__ w1, const float* __restrict__ b1) {
    constexpr int M_IN = 13, NC = 7, CBASE = 0;
    extern __shared__ char smem[];
    __shared__ float eas[640];
    const uint32_t sb = s2u(smem);
    const int tid = threadIdx.x, wid = tid >> 5, lane = tid & 31;
    const int tile = blockIdx.x;

    msg_prologue<NC, CBASE>(sb, smem, eas, ea, w1, b1, tile, tid);

    const int m0 = wid * 16;
    const int r0 = lane >> 2;
    const int e0 = tile * 128 + m0 + r0;
    const int e1 = e0 + 8;
    int src0 = 0, dst0 = -1, src1 = 0, dst1 = -1;
    if (e0 < NE) { src0 = g_src[e0]; dst0 = g_dst[e0]; }
    if (e1 < NE) { src1 = g_src[e1]; dst1 = g_dst[e1]; }

    const uint32_t lrow = (lane & 15);
    const uint32_t kh16 = (lane >> 4) * 16;

    float av[8][4];
#pragma unroll
    for (int nb = 0; nb < 8; nb++)
#pragma unroll
        for (int q = 0; q < 4; q++) av[nb][q] = 0.f;

    int bufc = 0;
    for (int c = 0; c < NC; c++) {
        if (c + 1 == NC) cp_wait<0>(); else cp_wait<1>();
        __syncthreads();
        if (c + 2 < NC) {
            int b2i = bufc + 2; if (b2i >= 3) b2i -= 3;
            copyB(CBASE + c + 2, sb + SM_B + (uint32_t)b2i * SM_BUF, tid);
            cp_commit();
        }
        const uint32_t Bb = sb + SM_B + (uint32_t)bufc * SM_BUF;
        if (++bufc == 3) bufc = 0;
        float d[8][4];
#pragma unroll
        for (int nb = 0; nb < 8; nb++)
#pragma unroll
            for (int q = 0; q < 4; q++) d[nb][q] = 0.f;
#pragma unroll
        for (int ks = 0; ks < 8; ks++) {
            uint32_t a[4];
            ldsm4(a, sb + (m0 + lrow) * 272 + ks * 32 + kh16);
#pragma unroll
            for (int nb2 = 0; nb2 < 4; nb2++) {
                uint32_t b[4];
                ldsm4(b, Bb + (nb2 * 16 + lrow) * 272 + ks * 32 + kh16);
                mma16816(d[2 * nb2],     a, b[0], b[2]);
                mma16816(d[2 * nb2 + 1], a, b[1], b[3]);
            }
        }
        const int i0 = min(2 * c, M_IN - 1), i1 = min(2 * c + 1, M_IN - 1);
        const float x00 = xin[(size_t)src0 * M_IN + i0];
        const float x01 = xin[(size_t)src0 * M_IN + i1];
        const float x10 = xin[(size_t)src1 * M_IN + i0];
        const float x11 = xin[(size_t)src1 * M_IN + i1];
#pragma unroll
        for (int nb = 0; nb < 8; nb++) {
            const float xsa = (nb < 4) ? x00 : x01;
            const float xsb = (nb < 4) ? x10 : x11;
            av[nb][0] = fmaf(xsa, d[nb][0], av[nb][0]);
            av[nb][1] = fmaf(xsa, d[nb][1], av[nb][1]);
            av[nb][2] = fmaf(xsb, d[nb][2], av[nb][2]);
            av[nb][3] = fmaf(xsb, d[nb][3], av[nb][3]);
        }
    }

    const int oc = (lane & 3) * 2;
#pragma unroll
    for (int nb = 0; nb < 4; nb++) {
        const int o = nb * 8 + oc;
        if (dst0 >= 0) {
            atomicAdd(acc + (size_t)dst0 * 32 + o,     av[nb][0] + av[nb + 4][0] + g_y[(size_t)src0 * 32 + o]);
            atomicAdd(acc + (size_t)dst0 * 32 + o + 1, av[nb][1] + av[nb + 4][1] + g_y[(size_t)src0 * 32 + o + 1]);
        }
        if (dst1 >= 0) {
            atomicAdd(acc + (size_t)dst1 * 32 + o,     av[nb][2] + av[nb + 4][2] + g_y[(size_t)src1 * 32 + o]);
            atomicAdd(acc + (size_t)dst1 * 32 + o + 1, av[nb][3] + av[nb + 4][3] + g_y[(size_t)src1 * 32 + o + 1]);
        }
    }
}

// -------- M_OUT=64 msg: 4x2 warp tiling (32 edges x 32 n per warp) ---------
// Per kstep: 2 A ldsm + 2 B ldsm + 8 MMA (was 1+4+8): total CTA ldsm traffic
// drops 20% (the L1=62.8% hotspot). elu-fused x staging as in R15.
template<int M_IN, int NC, int CBASE, int DO_ELU>
__global__ void __launch_bounds__(256, 2)
msg_mma64_kernel(const float* __restrict__ xin, float* __restrict__ acc,
                 const float* __restrict__ ea,
                 const float* __restrict__ w1, const float* __restrict__ b1) {
    extern __shared__ char smem[];
    __shared__ float eas[640];
    const uint32_t sb = s2u(smem);
    const int tid = threadIdx.x, wid = tid >> 5, lane = tid & 31;
    const int tile = blockIdx.x;

    msg_prologue<NC, CBASE>(sb, smem, eas, ea, w1, b1, tile, tid);

    // x rows -> smem fp16 transposed x16[c][row]; elu when DO_ELU
    {
        const int r = tid >> 1;
        const int hh = tid & 1;
        const int e = tile * 128 + r;
        const int srcr = (e < NE) ? g_src[e] : 0;
        const float4* xrow = (const float4*)(xin + (size_t)srcr * M_IN + hh * (M_IN / 2));
        __half* xsw = (__half*)(smem + SM_X);
#pragma unroll
        for (int j = 0; j < M_IN / 8; j++) {
            float4 v = xrow[j];
            if (DO_ELU) { v.x = eluf(v.x); v.y = eluf(v.y); v.z = eluf(v.z); v.w = eluf(v.w); }
            const int c0 = hh * (M_IN / 2) + j * 4;
            xsw[(c0 + 0) * 128 + r] = __float2half(v.x);
            xsw[(c0 + 1) * 128 + r] = __float2half(v.y);
            xsw[(c0 + 2) * 128 + r] = __float2half(v.z);
            xsw[(c0 + 3) * 128 + r] = __float2half(v.w);
        }
    }

    const int mg = wid >> 1;            // edge group 0..3 (32 edges each)
    const int ng = wid & 1;             // n group 0..1   (32 n each)
    const int m0 = mg * 32;
    const int n0 = ng * 32;
    const int r0 = lane >> 2;

    // 4 edges per lane: m0 + mf*16 + half*8 + r0
    int srcL[4], dstL[4];
#pragma unroll
    for (int mf = 0; mf < 2; mf++)
#pragma unroll
        for (int hf = 0; hf < 2; hf++) {
            const int e = tile * 128 + m0 + mf * 16 + hf * 8 + r0;
            srcL[mf * 2 + hf] = (e < NE) ? g_src[e] : 0;
            dstL[mf * 2 + hf] = (e < NE) ? g_dst[e] : -1;
        }

    const uint32_t lrow = (lane & 15);
    const uint32_t kh16 = (lane >> 4) * 16;
    const __half* xsr = (const __half*)(smem + SM_X);

    float av[8][4];                     // [mf*4 + nf*2 + h][q]
#pragma unroll
    for (int f = 0; f < 8; f++)
#pragma unroll
        for (int q = 0; q < 4; q++) av[f][q] = 0.f;

    int bufc = 0;
    for (int c = 0; c < NC; c++) {
        if (c + 1 == NC) cp_wait<0>(); else cp_wait<1>();
        __syncthreads();
        if (c + 2 < NC) {
            int b2i = bufc + 2; if (b2i >= 3) b2i -= 3;
            copyB(CBASE + c + 2, sb + SM_B + (uint32_t)b2i * SM_BUF, tid);
            cp_commit();
        }
        const uint32_t Bb = sb + SM_B + (uint32_t)bufc * SM_BUF;
        if (++bufc == 3) bufc = 0;
        float d[8][4];
#pragma unroll
        for (int f = 0; f < 8; f++)
#pragma unroll
            for (int q = 0; q < 4; q++) d[f][q] = 0.f;

#pragma unroll
        for (int ks = 0; ks < 8; ks++) {
            uint32_t a0[4], a1[4], b0[4], b1r[4];
            ldsm4(a0, sb + (m0 + lrow) * 272 + ks * 32 + kh16);
            ldsm4(a1, sb + (m0 + 16 + lrow) * 272 + ks * 32 + kh16);
            ldsm4(b0, Bb + (n0 + lrow) * 272 + ks * 32 + kh16);
            ldsm4(b1r, Bb + (n0 + 16 + lrow) * 272 + ks * 32 + kh16);
            mma16816(d[0], a0, b0[0],  b0[2]);
            mma16816(d[1], a0, b0[1],  b0[3]);
            mma16816(d[2], a0, b1r[0], b1r[2]);
            mma16816(d[3], a0, b1r[1], b1r[3]);
            mma16816(d[4], a1, b0[0],  b0[2]);
            mma16816(d[5], a1, b0[1],  b0[3]);
            mma16816(d[6], a1, b1r[0], b1r[2]);
            mma16816(d[7], a1, b1r[1], b1r[3]);
        }

        // x-fold: x value per (mf, half)
        const float xv[4] = {
            __half2float(xsr[c * 128 + m0 + r0]),
            __half2float(xsr[c * 128 + m0 + 8 + r0]),
            __half2float(xsr[c * 128 + m0 + 16 + r0]),
            __half2float(xsr[c * 128 + m0 + 24 + r0]) };
#pragma unroll
        for (int mf = 0; mf < 2; mf++)
#pragma unroll
            for (int nf2 = 0; nf2 < 4; nf2++) {
                const int f = mf * 4 + nf2;
                av[f][0] = fmaf(xv[mf * 2],     d[f][0], av[f][0]);
                av[f][1] = fmaf(xv[mf * 2],     d[f][1], av[f][1]);
                av[f][2] = fmaf(xv[mf * 2 + 1], d[f][2], av[f][2]);
                av[f][3] = fmaf(xv[mf * 2 + 1], d[f][3], av[f][3]);
            }
    }

    // scatter: lane owns 4 edges x 8 output cols
    const int oc = (lane & 3) * 2;
#pragma unroll
    for (int mf = 0; mf < 2; mf++)
#pragma unroll
        for (int nf = 0; nf < 2; nf++)
#pragma unroll
            for (int h = 0; h < 2; h++) {
                const int f = mf * 4 + nf * 2 + h;
                const int o = n0 + nf * 16 + h * 8 + oc;
                const int dA = dstL[mf * 2], sA = srcL[mf * 2];
                const int dB = dstL[mf * 2 + 1], sB = srcL[mf * 2 + 1];
                if (dA >= 0) {
                    atomicAdd(acc + (size_t)dA * 64 + o,     av[f][0] + g_y[(size_t)sA * 64 + o]);
                    atomicAdd(acc + (size_t)dA * 64 + o + 1, av[f][1] + g_y[(size_t)sA * 64 + o + 1]);
                }
                if (dB >= 0) {
                    atomicAdd(acc + (size_t)dB * 64 + o,     av[f][2] + g_y[(size_t)sB * 64 + o]);
                    atomicAdd(acc + (size_t)dB * 64 + o + 1, av[f][3] + g_y[(size_t)sB * 64 + o + 1]);
                }
            }
}

// ---------------- final MLP -------------------------------------------------
__global__ void __launch_bounds__(128)
mlp_kernel(const float* __restrict__ f1w, const float* __restrict__ f1b,
           const float* __restrict__ f2w, const float* __restrict__ f2b,
           const float* __restrict__ f3w, const float* __restrict__ f3b,
           float* __restrict__ out) {
    int g = blockIdx.x * blockDim.x + threadIdx.x;
    if (g >= NG) return;
    float inv = 1.f / fmaxf(g_cnt[g], 1.f);
    const float* sr = g_sums + g * 64;
    float h1[32];
#pragma unroll
    for (int j = 0; j < 32; j++) {
        float s = 0.f;
#pragma unroll
        for (int i = 0; i < 64; i++) s = fmaf(sr[i], f1w[i * 32 + j], s);
        h1[j] = eluf(fmaf(s, inv, f1b[j]));
    }
    float h2[16];
#pragma unroll
    for (int j = 0; j < 16; j++) {
        float s = f2b[j];
#pragma unroll
        for (int i = 0; i < 32; i++) s = fmaf(h1[i], f2w[i * 16 + j], s);
        h2[j] = eluf(s);
    }
    float s = f3b[0];
#pragma unroll
    for (int i = 0; i < 16; i++) s = fmaf(h2[i], f3w[i], s);
    out[g] = s;
}

// ---------------- driver ----------------------------------------------------
extern "C" void kernel_launch(void* const* d_in, const int* in_sizes, int n_in,
                              void* d_out, int out_size) {
    const float* x   = (const float*)d_in[0];
    const void*  ei  = d_in[1];
    const float* ea  = (const float*)d_in[2];
    const void*  bat = d_in[3];
    const float* W[24];
    for (int i = 0; i < 24; i++) W[i] = (const float*)d_in[4 + i];
    float* out = (float*)d_out;

    float *acc, *acc2;
    cudaGetSymbolAddress((void**)&acc, g_acc);
    cudaGetSymbolAddress((void**)&acc2, g_acc2);

    cudaFuncSetAttribute(msg_mma1_kernel,                  cudaFuncAttributeMaxDynamicSharedMemorySize, SMEM_BYTES);
    cudaFuncSetAttribute(msg_mma64_kernel<32, 32, 7, 1>,   cudaFuncAttributeMaxDynamicSharedMemorySize, SMEM_BYTES);
    cudaFuncSetAttribute(msg_mma64_kernel<64, 64, 39, 1>,  cudaFuncAttributeMaxDynamicSharedMemorySize, SMEM_BYTES);

    // merged prep: convert + pool-zero + w2prep(all) + layer-1 rootxb2
    prep_kernel<<<PREP_B_CONV + PREP_B_W2 + PREP_B_ROOT, 256>>>(
        ei, bat, W[2], W[8], W[14], x, W[4], W[5], W[3], acc);

    // layer 1: 13 -> 32
    msg_mma1_kernel<<<NTILES, 256, SMEM_BYTES>>>(x, acc, ea, W[0], W[1]);

    // transition 1->2, then layer 2 (4x2 tiling, elu fused into x staging)
    trans_kernel<32><<<NN / 4, 256>>>(acc, W[10], W[11], W[9], acc2);
    msg_mma64_kernel<32, 32, 7, 1><<<NTILES, 256, SMEM_BYTES>>>(acc, acc2, ea, W[6], W[7]);

    // transition 2->3, then layer 3
    trans_kernel<64><<<NN / 4, 256>>>(acc2, W[16], W[17], W[15], acc);
    msg_mma64_kernel<64, 64, 39, 1><<<NTILES, 256, SMEM_BYTES>>>(acc2, acc, ea, W[12], W[13]);

    // layer-3 elu + pooling, then head
    elu_pool_kernel<<<(NN + 31) / 32, 256>>>(acc);
    mlp_kernel<<<(NG + 127) / 128, 128>>>(W[18], W[19], W[20], W[21], W[22], W[23], out);
}

// round 17
// speedup vs baseline: 1.0731x; 1.0090x over previous
#include <cuda_runtime.h>
#include <cuda_fp16.h>
#include <math.h>
#include <stdint.h>

#define NE 50000
#define NN 25000
#define NG 1024
#define HID 128
#define NTILES 391

// msg smem (dynamic): A [128x272B] | B buf0|buf1|buf2 (64x272B each) | X16
#define SM_B      34816
#define SM_BUF    17408
#define SM_X      87040
#define SMEM_BYTES 103424

__device__ __align__(256) unsigned char g_w2s[103 * 16384];   // fp16 w2T chunks [64x256B]
__device__ float g_acc[NN * 64];
__device__ float g_acc2[NN * 64];
__device__ float g_y[NN * 64];        // f @ b2 per node
__device__ float g_sums[NG * 64];
__device__ float g_cnt[NG];
__device__ int g_src[NE], g_dst[NE], g_batch[NN];

__device__ __forceinline__ float eluf(float v) { return v > 0.f ? v : expm1f(v); }
__device__ __forceinline__ uint32_t s2u(const void* p) {
    uint32_t a;
    asm("{ .reg .u64 t; cvta.to.shared.u64 t, %1; cvt.u32.u64 %0, t; }" : "=r"(a) : "l"(p));
    return a;
}
__device__ __forceinline__ void cp16(uint32_t s, const void* g) {
    asm volatile("cp.async.cg.shared.global [%0], [%1], 16;" :: "r"(s), "l"(g));
}
__device__ __forceinline__ void cp_commit() { asm volatile("cp.async.commit_group;" ::: "memory"); }
template<int N> __device__ __forceinline__ void cp_wait() { asm volatile("cp.async.wait_group %0;" :: "n"(N) : "memory"); }
__device__ __forceinline__ void ldsm4(uint32_t* r, uint32_t a) {
    asm volatile("ldmatrix.sync.aligned.m8n8.x4.shared.b16 {%0,%1,%2,%3}, [%4];"
                 : "=r"(r[0]), "=r"(r[1]), "=r"(r[2]), "=r"(r[3]) : "r"(a));
}
__device__ __forceinline__ void mma16816(float* d, const uint32_t* a, uint32_t b0, uint32_t b1) {
    asm volatile("mma.sync.aligned.m16n8k16.row.col.f32.f16.f16.f32 "
                 "{%0,%1,%2,%3}, {%4,%5,%6,%7}, {%8,%9}, {%0,%1,%2,%3};"
                 : "+f"(d[0]), "+f"(d[1]), "+f"(d[2]), "+f"(d[3])
                 : "r"(a[0]), "r"(a[1]), "r"(a[2]), "r"(a[3]), "r"(b0), "r"(b1));
}

// ---------------- merged prep: convert + w2prep + layer-1 rootxb2 ----------
#define PREP_B_CONV 256
#define PREP_B_W2   3296
#define PREP_B_ROOT 3125
__global__ void prep_kernel(const void* __restrict__ ei, const void* __restrict__ bat,
                            const float* __restrict__ w2a, const float* __restrict__ w2b,
                            const float* __restrict__ w2c,
                            const float* __restrict__ x, const float* __restrict__ root,
                            const float* __restrict__ bias, const float* __restrict__ b2,
                            float* __restrict__ acc) {
    const int b = blockIdx.x;
    if (b < PREP_B_CONV) {
        const long long* e64 = (const long long*)ei;
        int is64 = 1;
#pragma unroll
        for (int i = 0; i < 32; i++) {
            long long v = e64[i];
            if (v < 0 || v >= (long long)NN) { is64 = 0; break; }
        }
        int t = b * 256 + threadIdx.x;
        if (t < NE) {
            if (is64) { g_src[t] = (int)((const long long*)ei)[t]; g_dst[t] = (int)((const long long*)ei)[NE + t]; }
            else      { g_src[t] = ((const int*)ei)[t];            g_dst[t] = ((const int*)ei)[NE + t]; }
        }
        if (t < NN) g_batch[t] = is64 ? (int)((const long long*)bat)[t] : ((const int*)bat)[t];
        if (t < NG * 64) g_sums[t] = 0.f;
        if (t < NG) g_cnt[t] = 0.f;
    } else if (b < PREP_B_CONV + PREP_B_W2) {
        int t = (b - PREP_B_CONV) * 256 + threadIdx.x;
        if (t >= 103 * 8192) return;
        int c = t >> 13, rem = t & 8191, r = rem >> 7, k = rem & 127;
        const float* w2; int cb, sz;
        if (c < 7)       { w2 = w2a; cb = 0;  sz = 13 * 32; }
        else if (c < 39) { w2 = w2b; cb = 7;  sz = 32 * 64; }
        else             { w2 = w2c; cb = 39; sz = 64 * 64; }
        int n = (c - cb) * 64 + r;
        float v = (n < sz) ? w2[k * sz + n] : 0.f;
        *(__half*)(g_w2s + (size_t)c * 16384 + r * 256 + k * 2) = __float2half(v);
    } else {
        int t = (b - PREP_B_CONV - PREP_B_W2) * 256 + threadIdx.x;
        if (t >= NN * 32) return;
        int n = t >> 5, o = t & 31;
        const float* xr = x + n * 13;
        float s = bias[o], y = 0.f;
#pragma unroll
        for (int i = 0; i < 13; i++) {
            float xv = xr[i];
            s = fmaf(xv, root[i * 32 + o], s);
            y = fmaf(xv, b2[i * 32 + o], y);
        }
        acc[t] = s;
        g_y[t] = y;
    }
}

// -------- layer transition: acc_out = elu(acc_in)@root+bias; y = elu@b2 ----
template<int MI>
__global__ void __launch_bounds__(256)
trans_kernel(const float* __restrict__ acc_in,
             const float* __restrict__ root, const float* __restrict__ bias,
             const float* __restrict__ b2, float* __restrict__ acc_out) {
    __shared__ float f[4][MI];
    const int tid = threadIdx.x;
    const int n0 = blockIdx.x * 4;
    if (tid < 4 * MI) {
        int n = tid / MI, i = tid - n * MI;
        f[n][i] = eluf(acc_in[(size_t)(n0 + n) * MI + i]);
    }
    __syncthreads();
    const int n = tid >> 6, o = tid & 63;
    float s = bias[o], y = 0.f;
#pragma unroll
    for (int i = 0; i < MI; i++) {
        float fv = f[n][i];
        s = fmaf(fv, root[i * 64 + o], s);
        y = fmaf(fv, b2[i * 64 + o], y);
    }
    acc_out[(size_t)(n0 + n) * 64 + o] = s;
    g_y[(size_t)(n0 + n) * 64 + o] = y;
}

// -------- layer-3 elu + pooling with run-length aggregation ----------------
__global__ void __launch_bounds__(256)
elu_pool_kernel(const float* __restrict__ acc) {
    const int tid = threadIdx.x;
    const int o = tid & 63;
    const int grp = tid >> 6;
    const int n0 = blockIdx.x * 32 + grp * 8;
    float s = 0.f;
    int curg = -1;
    for (int j = 0; j < 8; j++) {
        const int n = n0 + j;
        if (n >= NN) break;
        const int g = g_batch[n];
        const float v = eluf(acc[(size_t)n * 64 + o]);
        if (g != curg) {
            if (curg >= 0) atomicAdd(&g_sums[curg * 64 + o], s);
            curg = g; s = v;
        } else s += v;
    }
    if (curg >= 0) atomicAdd(&g_sums[curg * 64 + o], s);
    if (o == 0) {
        float c = 0.f; int cg = -1;
        for (int j = 0; j < 8; j++) {
            const int n = n0 + j;
            if (n >= NN) break;
            const int g = g_batch[n];
            if (g != cg) { if (cg >= 0) atomicAdd(&g_cnt[cg], c); cg = g; c = 1.f; }
            else c += 1.f;
        }
        if (cg >= 0) atomicAdd(&g_cnt[cg], c);
    }
}

__device__ __forceinline__ void copyB(int cabs, uint32_t dst, int tid) {
    const unsigned char* gb = g_w2s + (size_t)cabs * 16384;
    for (int idx = tid; idx < 1024; idx += 256) {
        int r = idx >> 4, s = idx & 15;
        cp16(dst + r * 272 + s * 16, gb + r * 256 + s * 16);
    }
}

// shared prologue: B kick-off + ea staging + h tile
template<int NC, int CBASE>
__device__ __forceinline__ void msg_prologue(uint32_t sb, char* smem, float* eas,
                                             const float* ea, const float* w1,
                                             const float* b1, int tile, int tid) {
    copyB(CBASE, sb + SM_B, tid);
    cp_commit();
    if (NC > 1) { copyB(CBASE + 1, sb + SM_B + SM_BUF, tid); cp_commit(); }
    {
        const int gbase = tile * 640;
        for (int idx = tid; idx < 640; idx += 256)
            eas[idx] = (gbase + idx < NE * 5) ? ea[gbase + idx] : 0.f;
    }
    const int kp = tid & 63, k2 = kp * 2;
    float wv[10], bv0, bv1;
#pragma unroll
    for (int d = 0; d < 5; d++) {
        wv[2 * d]     = w1[d * HID + k2];
        wv[2 * d + 1] = w1[d * HID + k2 + 1];
    }
    bv0 = b1[k2]; bv1 = b1[k2 + 1];
    __syncthreads();
    {
        const int rbase = tid >> 6;
        const int ecnt = min(128, NE - tile * 128);
#pragma unroll 8
        for (int j = 0; j < 32; j++) {
            const int r = rbase + 4 * j;
            uint32_t packed = 0;
            if (r < ecnt) {
                const float* a = eas + r * 5;
                float s0 = bv0, s1 = bv1;
                s0 = fmaf(a[0], wv[0], s0); s1 = fmaf(a[0], wv[1], s1);
                s0 = fmaf(a[1], wv[2], s0); s1 = fmaf(a[1], wv[3], s1);
                s0 = fmaf(a[2], wv[4], s0); s1 = fmaf(a[2], wv[5], s1);
                s0 = fmaf(a[3], wv[6], s0); s1 = fmaf(a[3], wv[7], s1);
                s0 = fmaf(a[4], wv[8], s0); s1 = fmaf(a[4], wv[9], s1);
                s0 = fmaxf(s0, 0.f); s1 = fmaxf(s1, 0.f);
                __half h0 = __float2half(s0), h1 = __float2half(s1);
                packed = ((uint32_t)__half_as_ushort(h1) << 16) | __half_as_ushort(h0);
            }
            *(uint32_t*)(smem + r * 272 + kp * 4) = packed;
        }
    }
}

// -------- LAYER-1 msg: 4x2 warp tiling ------------------------------------
// Warp (mg, ng): 32 edges x 32 B-rows. Chunk rows [0,32)=i0=2c (o 0..31),
// rows [32,64)=i1=2c+1 (same o range). Both n-groups accumulate the same o
// columns for the same edges with different i -> merged by the atomicAdd.
__global__ void __launch_bounds__(256, 2)
msg_mma1_kernel(const float* __restrict__ xin, float* __restrict__ acc,
                const float* __restrict__ ea,
                const float* __restrict__ w1, const float* __restrict__ b1) {
    constexpr int M_IN = 13, NC = 7, CBASE = 0;
    extern __shared__ char smem[];
    __shared__ float eas[640];
    const uint32_t sb = s2u(smem);
    const int tid = threadIdx.x, wid = tid >> 5, lane = tid & 31;
    const int tile = blockIdx.x;

    msg_prologue<NC, CBASE>(sb, smem, eas, ea, w1, b1, tile, tid);

    const int mg = wid >> 1;
    const int ng = wid & 1;             // 0 -> i=2c rows, 1 -> i=2c+1 rows
    const int m0 = mg * 32;
    const int n0 = ng * 32;
    const int r0 = lane >> 2;

    int srcL[4], dstL[4];
#pragma unroll
    for (int mf = 0; mf < 2; mf++)
#pragma unroll
        for (int hf = 0; hf < 2; hf++) {
            const int e = tile * 128 + m0 + mf * 16 + hf * 8 + r0;
            srcL[mf * 2 + hf] = (e < NE) ? g_src[e] : 0;
            dstL[mf * 2 + hf] = (e < NE) ? g_dst[e] : -1;
        }

    const uint32_t lrow = (lane & 15);
    const uint32_t kh16 = (lane >> 4) * 16;

    float av[8][4];                     // [mf*4 + nf*2 + h][q], nf in {0,1} covers o 0..31
#pragma unroll
    for (int f = 0; f < 8; f++)
#pragma unroll
        for (int q = 0; q < 4; q++) av[f][q] = 0.f;

    int bufc = 0;
    for (int c = 0; c < NC; c++) {
        if (c + 1 == NC) cp_wait<0>(); else cp_wait<1>();
        __syncthreads();
        if (c + 2 < NC) {
            int b2i = bufc + 2; if (b2i >= 3) b2i -= 3;
            copyB(CBASE + c + 2, sb + SM_B + (uint32_t)b2i * SM_BUF, tid);
            cp_commit();
        }
        const uint32_t Bb = sb + SM_B + (uint32_t)bufc * SM_BUF;
        if (++bufc == 3) bufc = 0;
        float d[8][4];
#pragma unroll
        for (int f = 0; f < 8; f++)
#pragma unroll
            for (int q = 0; q < 4; q++) d[f][q] = 0.f;

#pragma unroll
        for (int ks = 0; ks < 8; ks++) {
            uint32_t a0[4], a1[4], b0[4], b1r[4];
            ldsm4(a0, sb + (m0 + lrow) * 272 + ks * 32 + kh16);
            ldsm4(a1, sb + (m0 + 16 + lrow) * 272 + ks * 32 + kh16);
            ldsm4(b0, Bb + (n0 + lrow) * 272 + ks * 32 + kh16);
            ldsm4(b1r, Bb + (n0 + 16 + lrow) * 272 + ks * 32 + kh16);
            mma16816(d[0], a0, b0[0],  b0[2]);
            mma16816(d[1], a0, b0[1],  b0[3]);
            mma16816(d[2], a0, b1r[0], b1r[2]);
            mma16816(d[3], a0, b1r[1], b1r[3]);
            mma16816(d[4], a1, b0[0],  b0[2]);
            mma16816(d[5], a1, b0[1],  b0[3]);
            mma16816(d[6], a1, b1r[0], b1r[2]);
            mma16816(d[7], a1, b1r[1], b1r[3]);
        }

        // x-fold: this warp's i index = 2c + ng
        const int ii = min(2 * c + ng, M_IN - 1);
        const float xv[4] = {
            xin[(size_t)srcL[0] * M_IN + ii],
            xin[(size_t)srcL[1] * M_IN + ii],
            xin[(size_t)srcL[2] * M_IN + ii],
            xin[(size_t)srcL[3] * M_IN + ii] };
#pragma unroll
        for (int mf = 0; mf < 2; mf++)
#pragma unroll
            for (int nf2 = 0; nf2 < 4; nf2++) {
                const int f = mf * 4 + nf2;
                av[f][0] = fmaf(xv[mf * 2],     d[f][0], av[f][0]);
                av[f][1] = fmaf(xv[mf * 2],     d[f][1], av[f][1]);
                av[f][2] = fmaf(xv[mf * 2 + 1], d[f][2], av[f][2]);
                av[f][3] = fmaf(xv[mf * 2 + 1], d[f][3], av[f][3]);
            }
    }

    // scatter: o column = (row within n-group) & 31; y added by ng==0 only
    const int oc = (lane & 3) * 2;
#pragma unroll
    for (int mf = 0; mf < 2; mf++)
#pragma unroll
        for (int nf = 0; nf < 2; nf++)
#pragma unroll
            for (int h = 0; h < 2; h++) {
                const int f = mf * 4 + nf * 2 + h;
                const int o = nf * 16 + h * 8 + oc;     // 0..31
                const int dA = dstL[mf * 2], sA = srcL[mf * 2];
                const int dB = dstL[mf * 2 + 1], sB = srcL[mf * 2 + 1];
                const float yA0 = ng ? 0.f : g_y[(size_t)sA * 32 + o];
                const float yA1 = ng ? 0.f : g_y[(size_t)sA * 32 + o + 1];
                const float yB0 = ng ? 0.f : g_y[(size_t)sB * 32 + o];
                const float yB1 = ng ? 0.f : g_y[(size_t)sB * 32 + o + 1];
                if (dA >= 0) {
                    atomicAdd(acc + (size_t)dA * 32 + o,     av[f][0] + yA0);
                    atomicAdd(acc + (size_t)dA * 32 + o + 1, av[f][1] + yA1);
                }
                if (dB >= 0) {
                    atomicAdd(acc + (size_t)dB * 32 + o,     av[f][2] + yB0);
                    atomicAdd(acc + (size_t)dB * 32 + o + 1, av[f][3] + yB1);
                }
            }
}

// -------- M_OUT=64 msg: 4x2 warp tiling + elu-fused x staging (R16) --------
template<int M_IN, int NC, int CBASE, int DO_ELU>
__global__ void __launch_bounds__(256, 2)
msg_mma64_kernel(const float* __restrict__ xin, float* __restrict__ acc,
                 const float* __restrict__ ea,
                 const float* __restrict__ w1, const float* __restrict__ b1) {
    extern __shared__ char smem[];
    __shared__ float eas[640];
    const uint32_t sb = s2u(smem);
    const int tid = threadIdx.x, wid = tid >> 5, lane = tid & 31;
    const int tile = blockIdx.x;

    msg_prologue<NC, CBASE>(sb, smem, eas, ea, w1, b1, tile, tid);

    {
        const int r = tid >> 1;
        const int hh = tid & 1;
        const int e = tile * 128 + r;
        const int srcr = (e < NE) ? g_src[e] : 0;
        const float4* xrow = (const float4*)(xin + (size_t)srcr * M_IN + hh * (M_IN / 2));
        __half* xsw = (__half*)(smem + SM_X);
#pragma unroll
        for (int j = 0; j < M_IN / 8; j++) {
            float4 v = xrow[j];
            if (DO_ELU) { v.x = eluf(v.x); v.y = eluf(v.y); v.z = eluf(v.z); v.w = eluf(v.w); }
            const int c0 = hh * (M_IN / 2) + j * 4;
            xsw[(c0 + 0) * 128 + r] = __float2half(v.x);
            xsw[(c0 + 1) * 128 + r] = __float2half(v.y);
            xsw[(c0 + 2) * 128 + r] = __float2half(v.z);
            xsw[(c0 + 3) * 128 + r] = __float2half(v.w);
        }
    }

    const int mg = wid >> 1;
    const int ng = wid & 1;
    const int m0 = mg * 32;
    const int n0 = ng * 32;
    const int r0 = lane >> 2;

    int srcL[4], dstL[4];
#pragma unroll
    for (int mf = 0; mf < 2; mf++)
#pragma unroll
        for (int hf = 0; hf < 2; hf++) {
            const int e = tile * 128 + m0 + mf * 16 + hf * 8 + r0;
            srcL[mf * 2 + hf] = (e < NE) ? g_src[e] : 0;
            dstL[mf * 2 + hf] = (e < NE) ? g_dst[e] : -1;
        }

    const uint32_t lrow = (lane & 15);
    const uint32_t kh16 = (lane >> 4) * 16;
    const __half* xsr = (const __half*)(smem + SM_X);

    float av[8][4];
#pragma unroll
    for (int f = 0; f < 8; f++)
#pragma unroll
        for (int q = 0; q < 4; q++) av[f][q] = 0.f;

    int bufc = 0;
    for (int c = 0; c < NC; c++) {
        if (c + 1 == NC) cp_wait<0>(); else cp_wait<1>();
        __syncthreads();
        if (c + 2 < NC) {
            int b2i = bufc + 2; if (b2i >= 3) b2i -= 3;
            copyB(CBASE + c + 2, sb + SM_B + (uint32_t)b2i * SM_BUF, tid);
            cp_commit();
        }
        const uint32_t Bb = sb + SM_B + (uint32_t)bufc * SM_BUF;
        if (++bufc == 3) bufc = 0;
        float d[8][4];
#pragma unroll
        for (int f = 0; f < 8; f++)
#pragma unroll
            for (int q = 0; q < 4; q++) d[f][q] = 0.f;

#pragma unroll
        for (int ks = 0; ks < 8; ks++) {
            uint32_t a0[4], a1[4], b0[4], b1r[4];
            ldsm4(a0, sb + (m0 + lrow) * 272 + ks * 32 + kh16);
            ldsm4(a1, sb + (m0 + 16 + lrow) * 272 + ks * 32 + kh16);
            ldsm4(b0, Bb + (n0 + lrow) * 272 + ks * 32 + kh16);
            ldsm4(b1r, Bb + (n0 + 16 + lrow) * 272 + ks * 32 + kh16);
            mma16816(d[0], a0, b0[0],  b0[2]);
            mma16816(d[1], a0, b0[1],  b0[3]);
            mma16816(d[2], a0, b1r[0], b1r[2]);
            mma16816(d[3], a0, b1r[1], b1r[3]);
            mma16816(d[4], a1, b0[0],  b0[2]);
            mma16816(d[5], a1, b0[1],  b0[3]);
            mma16816(d[6], a1, b1r[0], b1r[2]);
            mma16816(d[7], a1, b1r[1], b1r[3]);
        }

        const float xv[4] = {
            __half2float(xsr[c * 128 + m0 + r0]),
            __half2float(xsr[c * 128 + m0 + 8 + r0]),
            __half2float(xsr[c * 128 + m0 + 16 + r0]),
            __half2float(xsr[c * 128 + m0 + 24 + r0]) };
#pragma unroll
        for (int mf = 0; mf < 2; mf++)
#pragma unroll
            for (int nf2 = 0; nf2 < 4; nf2++) {
                const int f = mf * 4 + nf2;
                av[f][0] = fmaf(xv[mf * 2],     d[f][0], av[f][0]);
                av[f][1] = fmaf(xv[mf * 2],     d[f][1], av[f][1]);
                av[f][2] = fmaf(xv[mf * 2 + 1], d[f][2], av[f][2]);
                av[f][3] = fmaf(xv[mf * 2 + 1], d[f][3], av[f][3]);
            }
    }

    const int oc = (lane & 3) * 2;
#pragma unroll
    for (int mf = 0; mf < 2; mf++)
#pragma unroll
        for (int nf = 0; nf < 2; nf++)
#pragma unroll
            for (int h = 0; h < 2; h++) {
                const int f = mf * 4 + nf * 2 + h;
                const int o = n0 + nf * 16 + h * 8 + oc;
                const int dA = dstL[mf * 2], sA = srcL[mf * 2];
                const int dB = dstL[mf * 2 + 1], sB = srcL[mf * 2 + 1];
                if (dA >= 0) {
                    atomicAdd(acc + (size_t)dA * 64 + o,     av[f][0] + g_y[(size_t)sA * 64 + o]);
                    atomicAdd(acc + (size_t)dA * 64 + o + 1, av[f][1] + g_y[(size_t)sA * 64 + o + 1]);
                }
                if (dB >= 0) {
                    atomicAdd(acc + (size_t)dB * 64 + o,     av[f][2] + g_y[(size_t)sB * 64 + o]);
                    atomicAdd(acc + (size_t)dB * 64 + o + 1, av[f][3] + g_y[(size_t)sB * 64 + o + 1]);
                }
            }
}

// ---------------- final MLP -------------------------------------------------
__global__ void __launch_bounds__(128)
mlp_kernel(const float* __restrict__ f1w, const float* __restrict__ f1b,
           const float* __restrict__ f2w, const float* __restrict__ f2b,
           const float* __restrict__ f3w, const float* __restrict__ f3b,
           float* __restrict__ out) {
    int g = blockIdx.x * blockDim.x + threadIdx.x;
    if (g >= NG) return;
    float inv = 1.f / fmaxf(g_cnt[g], 1.f);
    const float* sr = g_sums + g * 64;
    float h1[32];
#pragma unroll
    for (int j = 0; j < 32; j++) {
        float s = 0.f;
#pragma unroll
        for (int i = 0; i < 64; i++) s = fmaf(sr[i], f1w[i * 32 + j], s);
        h1[j] = eluf(fmaf(s, inv, f1b[j]));
    }
    float h2[16];
#pragma unroll
    for (int j = 0; j < 16; j++) {
        float s = f2b[j];
#pragma unroll
        for (int i = 0; i < 32; i++) s = fmaf(h1[i], f2w[i * 16 + j], s);
        h2[j] = eluf(s);
    }
    float s = f3b[0];
#pragma unroll
    for (int i = 0; i < 16; i++) s = fmaf(h2[i], f3w[i], s);
    out[g] = s;
}

// ---------------- driver ----------------------------------------------------
extern "C" void kernel_launch(void* const* d_in, const int* in_sizes, int n_in,
                              void* d_out, int out_size) {
    const float* x   = (const float*)d_in[0];
    const void*  ei  = d_in[1];
    const float* ea  = (const float*)d_in[2];
    const void*  bat = d_in[3];
    const float* W[24];
    for (int i = 0; i < 24; i++) W[i] = (const float*)d_in[4 + i];
    float* out = (float*)d_out;

    float *acc, *acc2;
    cudaGetSymbolAddress((void**)&acc, g_acc);
    cudaGetSymbolAddress((void**)&acc2, g_acc2);

    cudaFuncSetAttribute(msg_mma1_kernel,                  cudaFuncAttributeMaxDynamicSharedMemorySize, SMEM_BYTES);
    cudaFuncSetAttribute(msg_mma64_kernel<32, 32, 7, 1>,   cudaFuncAttributeMaxDynamicSharedMemorySize, SMEM_BYTES);
    cudaFuncSetAttribute(msg_mma64_kernel<64, 64, 39, 1>,  cudaFuncAttributeMaxDynamicSharedMemorySize, SMEM_BYTES);

    prep_kernel<<<PREP_B_CONV + PREP_B_W2 + PREP_B_ROOT, 256>>>(
        ei, bat, W[2], W[8], W[14], x, W[4], W[5], W[3], acc);

    // layer 1: 13 -> 32 (4x2 tiling)
    msg_mma1_kernel<<<NTILES, 256, SMEM_BYTES>>>(x, acc, ea, W[0], W[1]);

    // transition 1->2, then layer 2
    trans_kernel<32><<<NN / 4, 256>>>(acc, W[10], W[11], W[9], acc2);
    msg_mma64_kernel<32, 32, 7, 1><<<NTILES, 256, SMEM_BYTES>>>(acc, acc2, ea, W[6], W[7]);

    // transition 2->3, then layer 3
    trans_kernel<64><<<NN / 4, 256>>>(acc2, W[16], W[17], W[15], acc);
    msg_mma64_kernel<64, 64, 39, 1><<<NTILES, 256, SMEM_BYTES>>>(acc2, acc, ea, W[12], W[13]);

    // layer-3 elu + pooling, then head
    elu_pool_kernel<<<(NN + 31) / 32, 256>>>(acc);
    mlp_kernel<<<(NG + 127) / 128, 128>>>(W[18], W[19], W[20], W[21], W[22], W[23], out);
}